// round 8
// baseline (speedup 1.0000x reference)
#include <cuda_runtime.h>
#include <cuda_bf16.h>
#include <cstdint>
#include <math.h>

// Problem constants
#define BB   2
#define LL   4096
#define EE   512
#define HH   8
#define DD   64
#define WIN  128
#define NTOK (BB*LL)          // 8192
#define QKVN (3*EE)           // 1536

// ---------------------------------------------------------------------------
// Device scratch
// ---------------------------------------------------------------------------
__device__ float g_Q[BB*HH*LL*DD];
__device__ float g_K[BB*HH*LL*DD];
__device__ float g_V[BB*HH*LL*DD];
__device__ float g_O[BB*LL*EE];

// ---------------------------------------------------------------------------
// Helpers
// ---------------------------------------------------------------------------
__device__ __forceinline__ uint32_t f2tf32(float x) {
    uint32_t r;
    asm("cvt.rna.tf32.f32 %0, %1;" : "=r"(r) : "f"(x));
    return r;
}
__device__ __forceinline__ void split_tf32(float x, uint32_t& hi, uint32_t& lo) {
    uint32_t h = f2tf32(x);
    hi = h;
    lo = f2tf32(x - __uint_as_float(h));
}

__device__ __forceinline__ void mma_tf32(float* d, const uint32_t* a,
                                         const uint32_t* b) {
    asm volatile(
        "mma.sync.aligned.m16n8k8.row.col.f32.tf32.tf32.f32 "
        "{%0,%1,%2,%3}, {%4,%5,%6,%7}, {%8,%9}, {%0,%1,%2,%3};"
        : "+f"(d[0]), "+f"(d[1]), "+f"(d[2]), "+f"(d[3])
        : "r"(a[0]), "r"(a[1]), "r"(a[2]), "r"(a[3]),
          "r"(b[0]), "r"(b[1]));
}

__device__ __forceinline__ uint32_t smem_u32(const void* p) {
    uint32_t a;
    asm("{ .reg .u64 t; cvta.to.shared.u64 t, %1; cvt.u32.u64 %0, t; }"
        : "=r"(a) : "l"(p));
    return a;
}
__device__ __forceinline__ void cp16(uint32_t dst, const void* src) {
    asm volatile("cp.async.ca.shared.global [%0], [%1], 16;"
                 :: "r"(dst), "l"(src));
}
#define CP_COMMIT() asm volatile("cp.async.commit_group;" ::: "memory")

// ---------------------------------------------------------------------------
// tf32 mma.sync GEMM with cp.async double-buffered pipeline.
//   C[M,N] = A[M,K] @ Bw[N,K]^T + bias, K = 512.
//   CTA tile 128x128, BK=32, 8 warps, warp tile 64x32.
// ---------------------------------------------------------------------------
#define SPAD 36
#define GSZ  (128 * SPAD)
#define GEMM_SMEM (4 * GSZ * 4)

__global__ __launch_bounds__(256) void tf32_gemm(
    const float* __restrict__ Ain, const float* __restrict__ Bw,
    const float* __restrict__ bias, float* __restrict__ outp, int mode)
{
    extern __shared__ float smg[];
    const uint32_t sbase = smem_u32(smg);

    const int tid = threadIdx.x;
    const int m0 = blockIdx.y * 128;
    const int n0 = blockIdx.x * 128;
    const float* A = (mode == 1) ? g_O : Ain;

    const int w    = tid >> 5;
    const int lane = tid & 31;
    const int g    = lane >> 2;
    const int c    = lane & 3;
    const int rm   = (w >> 2) * 64;
    const int cn   = (w & 3) * 32;

    float acc[4][4][4];
    #pragma unroll
    for (int mi = 0; mi < 4; mi++)
        #pragma unroll
        for (int ni = 0; ni < 4; ni++)
            #pragma unroll
            for (int r = 0; r < 4; r++) acc[mi][ni][r] = 0.f;

    const int lrow = tid >> 3;
    const int lk4  = (tid & 7) * 4;

    auto issue_chunk = [&](int kc, int p) {
        const float* Ag = A  + (size_t)m0 * EE + kc * 32;
        const float* Bg = Bw + (size_t)n0 * EE + kc * 32;
        #pragma unroll
        for (int i = 0; i < 4; i++) {
            int row = lrow + i * 32;
            cp16(sbase + (uint32_t)((p * GSZ + row * SPAD + lk4) * 4),
                 Ag + (size_t)row * EE + lk4);
            cp16(sbase + (uint32_t)(((2 + p) * GSZ + row * SPAD + lk4) * 4),
                 Bg + (size_t)row * EE + lk4);
        }
    };

    issue_chunk(0, 0);
    CP_COMMIT();

    for (int kc = 0; kc < 16; kc++) {
        const int p = kc & 1;
        if (kc < 15) {
            issue_chunk(kc + 1, p ^ 1);
            CP_COMMIT();
            asm volatile("cp.async.wait_group 1;" ::: "memory");
        } else {
            asm volatile("cp.async.wait_group 0;" ::: "memory");
        }
        __syncthreads();

        const float* Asp = smg + p * GSZ;
        const float* Bsp = smg + (2 + p) * GSZ;

        #pragma unroll
        for (int ks = 0; ks < 4; ks++) {
            uint32_t af[4][4], bf[4][2];
            #pragma unroll
            for (int mi = 0; mi < 4; mi++) {
                const float* base = Asp + (rm + mi * 16 + g) * SPAD + ks * 8;
                af[mi][0] = f2tf32(base[c]);
                af[mi][1] = f2tf32(base[8 * SPAD + c]);
                af[mi][2] = f2tf32(base[c + 4]);
                af[mi][3] = f2tf32(base[8 * SPAD + c + 4]);
            }
            #pragma unroll
            for (int ni = 0; ni < 4; ni++) {
                const float* base = Bsp + (cn + ni * 8 + g) * SPAD + ks * 8;
                bf[ni][0] = f2tf32(base[c]);
                bf[ni][1] = f2tf32(base[c + 4]);
            }
            #pragma unroll
            for (int mi = 0; mi < 4; mi++)
                #pragma unroll
                for (int ni = 0; ni < 4; ni++)
                    mma_tf32(acc[mi][ni], af[mi], bf[ni]);
        }
        __syncthreads();
    }

    float bv[4][2];
    #pragma unroll
    for (int ni = 0; ni < 4; ni++) {
        int gn = n0 + cn + ni * 8 + 2 * c;
        bv[ni][0] = bias[gn];
        bv[ni][1] = bias[gn + 1];
    }

    if (mode == 0) {
        const int gnb = n0 + cn;
        const int sel = gnb >> 9;
        const int h   = (gnb >> 6) & 7;
        const float scale = (sel == 0) ? 0.125f : 1.0f;
        float* dst = (sel == 0) ? g_Q : (sel == 1) ? g_K : g_V;
        #pragma unroll
        for (int mi = 0; mi < 4; mi++) {
            #pragma unroll
            for (int half = 0; half < 2; half++) {
                int gm  = m0 + rm + mi * 16 + g + half * 8;
                int bat = gm >> 12;
                int l   = gm & (LL - 1);
                size_t rowbase = (((size_t)(bat * HH + h) * LL) + l) * DD;
                #pragma unroll
                for (int ni = 0; ni < 4; ni++) {
                    int gn = n0 + cn + ni * 8 + 2 * c;
                    int d  = gn & 63;
                    float2 o;
                    o.x = (acc[mi][ni][half * 2 + 0] + bv[ni][0]) * scale;
                    o.y = (acc[mi][ni][half * 2 + 1] + bv[ni][1]) * scale;
                    *reinterpret_cast<float2*>(dst + rowbase + d) = o;
                }
            }
        }
    } else {
        #pragma unroll
        for (int mi = 0; mi < 4; mi++) {
            #pragma unroll
            for (int half = 0; half < 2; half++) {
                int gm = m0 + rm + mi * 16 + g + half * 8;
                #pragma unroll
                for (int ni = 0; ni < 4; ni++) {
                    int gn = n0 + cn + ni * 8 + 2 * c;
                    float2 o;
                    o.x = acc[mi][ni][half * 2 + 0] + bv[ni][0];
                    o.y = acc[mi][ni][half * 2 + 1] + bv[ni][1];
                    *reinterpret_cast<float2*>(outp + (size_t)gm * EE + gn) = o;
                }
            }
        }
    }
}

// ---------------------------------------------------------------------------
// Banded flash attention.
//   Q split into Qh/Ql planes once per block (2-MMA split path on A side).
//   K, V pre-rounded to tf32 at staging (single-term B side; no transpose).
//   scores = (Qh+Ql)·K_tf32 ; PV = (Ph+Pl)·V_tf32 — 2 MMAs each.
//   Planes: Qh | Ql | Ks | Vs | Ps, each [64][APAD]. 87 KB -> 2 CTAs/SM.
// ---------------------------------------------------------------------------
#define APAD 68
#define PL   (64 * APAD)
#define ATTN_SMEM (5 * PL * 4)

__global__ __launch_bounds__(128) void attn_mma()
{
    extern __shared__ float sm[];
    float* Qh = sm;
    float* Ql = sm + 1 * PL;
    float* Ks = sm + 2 * PL;
    float* Vs = sm + 3 * PL;
    float* Ps = sm + 4 * PL;

    const int q0 = blockIdx.x * 64;
    const int h  = blockIdx.y;
    const int b  = blockIdx.z;
    const int tid  = threadIdx.x;
    const int w    = tid >> 5;
    const int lane = tid & 31;
    const int g    = lane >> 2;
    const int c    = lane & 3;

    const size_t head_off = ((size_t)(b * HH + h) * LL) * DD;
    const float* Qg = g_Q + head_off;
    const float* Kg = g_K + head_off;
    const float* Vg = g_V + head_off;

    // Load Q tile [64][64], split hi/lo once
    #pragma unroll
    for (int i = 0; i < 8; i++) {
        int u = tid + i * 128;
        int row = u >> 4;
        int col = (u & 15) * 4;
        float4 v = *reinterpret_cast<const float4*>(&Qg[(size_t)(q0 + row) * DD + col]);
        uint32_t hx, lx, hy, ly, hz, lz, hw, lw;
        split_tf32(v.x, hx, lx); split_tf32(v.y, hy, ly);
        split_tf32(v.z, hz, lz); split_tf32(v.w, hw, lw);
        *reinterpret_cast<float4*>(&Qh[row * APAD + col]) =
            make_float4(__uint_as_float(hx), __uint_as_float(hy),
                        __uint_as_float(hz), __uint_as_float(hw));
        *reinterpret_cast<float4*>(&Ql[row * APAD + col]) =
            make_float4(__uint_as_float(lx), __uint_as_float(ly),
                        __uint_as_float(lz), __uint_as_float(lw));
    }

    float om[2] = {-1e30f, -1e30f};
    float ol[2] = {0.f, 0.f};
    float oacc[8][4];
    #pragma unroll
    for (int nt = 0; nt < 8; nt++)
        #pragma unroll
        for (int r = 0; r < 4; r++) oacc[nt][r] = 0.f;

    __syncthreads();

    const int row_lo = 16 * w + g;
    const int q_lo = q0 + row_lo;
    const int q_hi = q_lo + 8;

    for (int ch = 0; ch < 5; ch++) {
        const int kcc = q0 - 128 + ch * 64;
        if (kcc + 64 <= 0 || kcc >= LL) continue;

        // ---- stage K, V (tf32-rounded, natural layout) ----
        #pragma unroll
        for (int i = 0; i < 8; i++) {
            int u = tid + i * 128;
            int row = u >> 4;
            int col = (u & 15) * 4;
            int key = kcc + row;
            int kk = min(max(key, 0), LL - 1);
            float4 kv = *reinterpret_cast<const float4*>(&Kg[(size_t)kk * DD + col]);
            *reinterpret_cast<float4*>(&Ks[row * APAD + col]) =
                make_float4(__uint_as_float(f2tf32(kv.x)), __uint_as_float(f2tf32(kv.y)),
                            __uint_as_float(f2tf32(kv.z)), __uint_as_float(f2tf32(kv.w)));
            float4 vv = *reinterpret_cast<const float4*>(&Vg[(size_t)kk * DD + col]);
            *reinterpret_cast<float4*>(&Vs[row * APAD + col]) =
                make_float4(__uint_as_float(f2tf32(vv.x)), __uint_as_float(f2tf32(vv.y)),
                            __uint_as_float(f2tf32(vv.z)), __uint_as_float(f2tf32(vv.w)));
        }
        __syncthreads();

        // ---- scores S[16][64] per warp: (Qh+Ql)·K ----
        float sacc[8][4];
        #pragma unroll
        for (int nt = 0; nt < 8; nt++)
            #pragma unroll
            for (int r = 0; r < 4; r++) sacc[nt][r] = 0.f;

        #pragma unroll
        for (int ks = 0; ks < 8; ks++) {
            const int abase = row_lo * APAD + ks * 8;
            uint32_t ah[4], al[4];
            ah[0] = __float_as_uint(Qh[abase + c]);
            ah[1] = __float_as_uint(Qh[abase + 8 * APAD + c]);
            ah[2] = __float_as_uint(Qh[abase + c + 4]);
            ah[3] = __float_as_uint(Qh[abase + 8 * APAD + c + 4]);
            al[0] = __float_as_uint(Ql[abase + c]);
            al[1] = __float_as_uint(Ql[abase + 8 * APAD + c]);
            al[2] = __float_as_uint(Ql[abase + c + 4]);
            al[3] = __float_as_uint(Ql[abase + 8 * APAD + c + 4]);
            #pragma unroll
            for (int nt = 0; nt < 8; nt++) {
                const int bidx = (nt * 8 + g) * APAD + ks * 8;
                uint32_t bf[2];
                bf[0] = __float_as_uint(Ks[bidx + c]);
                bf[1] = __float_as_uint(Ks[bidx + c + 4]);
                mma_tf32(sacc[nt], ah, bf);
                mma_tf32(sacc[nt], al, bf);
            }
        }

        // ---- mask ----
        #pragma unroll
        for (int nt = 0; nt < 8; nt++) {
            #pragma unroll
            for (int r = 0; r < 4; r++) {
                int key = kcc + nt * 8 + 2 * c + (r & 1);
                int q   = (r >> 1) ? q_hi : q_lo;
                int dlt = q - key;
                bool ok = (key >= 0) && (key < LL) && (dlt != 0) &&
                          (dlt <= WIN) && (dlt >= -WIN);
                if (!ok) sacc[nt][r] = -1e30f;
            }
        }

        // ---- online softmax ----
        float mx0 = -1e30f, mx1 = -1e30f;
        #pragma unroll
        for (int nt = 0; nt < 8; nt++) {
            mx0 = fmaxf(mx0, fmaxf(sacc[nt][0], sacc[nt][1]));
            mx1 = fmaxf(mx1, fmaxf(sacc[nt][2], sacc[nt][3]));
        }
        mx0 = fmaxf(mx0, __shfl_xor_sync(0xffffffffu, mx0, 1));
        mx0 = fmaxf(mx0, __shfl_xor_sync(0xffffffffu, mx0, 2));
        mx1 = fmaxf(mx1, __shfl_xor_sync(0xffffffffu, mx1, 1));
        mx1 = fmaxf(mx1, __shfl_xor_sync(0xffffffffu, mx1, 2));

        float m0n = fmaxf(om[0], mx0);
        float m1n = fmaxf(om[1], mx1);
        float alpha0 = __expf(om[0] - m0n);
        float alpha1 = __expf(om[1] - m1n);

        float sum0 = 0.f, sum1 = 0.f;
        #pragma unroll
        for (int nt = 0; nt < 8; nt++) {
            float p0 = __expf(sacc[nt][0] - m0n);
            float p1 = __expf(sacc[nt][1] - m0n);
            float p2 = __expf(sacc[nt][2] - m1n);
            float p3 = __expf(sacc[nt][3] - m1n);
            sum0 += p0 + p1;
            sum1 += p2 + p3;
            *reinterpret_cast<float2*>(&Ps[row_lo * APAD + nt * 8 + 2 * c]) =
                make_float2(p0, p1);
            *reinterpret_cast<float2*>(&Ps[(row_lo + 8) * APAD + nt * 8 + 2 * c]) =
                make_float2(p2, p3);
        }
        sum0 += __shfl_xor_sync(0xffffffffu, sum0, 1);
        sum0 += __shfl_xor_sync(0xffffffffu, sum0, 2);
        sum1 += __shfl_xor_sync(0xffffffffu, sum1, 1);
        sum1 += __shfl_xor_sync(0xffffffffu, sum1, 2);

        ol[0] = ol[0] * alpha0 + sum0;
        ol[1] = ol[1] * alpha1 + sum1;
        om[0] = m0n;
        om[1] = m1n;

        #pragma unroll
        for (int nt = 0; nt < 8; nt++) {
            oacc[nt][0] *= alpha0;
            oacc[nt][1] *= alpha0;
            oacc[nt][2] *= alpha1;
            oacc[nt][3] *= alpha1;
        }
        __syncwarp();

        // ---- O += (Ph+Pl) @ V ----
        #pragma unroll
        for (int ks = 0; ks < 8; ks++) {
            const int pbase = row_lo * APAD + ks * 8;
            uint32_t ah[4], al[4];
            split_tf32(Ps[pbase + c],                ah[0], al[0]);
            split_tf32(Ps[pbase + 8 * APAD + c],     ah[1], al[1]);
            split_tf32(Ps[pbase + c + 4],            ah[2], al[2]);
            split_tf32(Ps[pbase + 8 * APAD + c + 4], ah[3], al[3]);
            #pragma unroll
            for (int nt = 0; nt < 8; nt++) {
                uint32_t bf[2];
                bf[0] = __float_as_uint(Vs[(ks * 8 + c) * APAD + nt * 8 + g]);
                bf[1] = __float_as_uint(Vs[(ks * 8 + c + 4) * APAD + nt * 8 + g]);
                mma_tf32(oacc[nt], ah, bf);
                mma_tf32(oacc[nt], al, bf);
            }
        }
        __syncthreads();
    }

    // ---- epilogue ----
    const float inv0 = 1.f / ol[0];
    const float inv1 = 1.f / ol[1];
    const size_t base_lo = ((size_t)(b * LL + q_lo) * HH + h) * DD;
    const size_t base_hi = ((size_t)(b * LL + q_hi) * HH + h) * DD;
    #pragma unroll
    for (int nt = 0; nt < 8; nt++) {
        int d = nt * 8 + 2 * c;
        *reinterpret_cast<float2*>(&g_O[base_lo + d]) =
            make_float2(oacc[nt][0] * inv0, oacc[nt][1] * inv0);
        *reinterpret_cast<float2*>(&g_O[base_hi + d]) =
            make_float2(oacc[nt][2] * inv1, oacc[nt][3] * inv1);
    }
}

// ---------------------------------------------------------------------------
// Entry point
// ---------------------------------------------------------------------------
extern "C" void kernel_launch(void* const* d_in, const int* in_sizes, int n_in,
                              void* d_out, int out_size)
{
    const float* x    = (const float*)d_in[0];   // [B,L,E]
    const float* wqkv = (const float*)d_in[1];   // [3E,E]
    const float* bqkv = (const float*)d_in[2];   // [3E]
    const float* wout = (const float*)d_in[3];   // [E,E]
    const float* bout = (const float*)d_in[4];   // [E]
    float* out = (float*)d_out;                  // [B,L,E]

    (void)in_sizes; (void)n_in; (void)out_size;

    cudaFuncSetAttribute(tf32_gemm, cudaFuncAttributeMaxDynamicSharedMemorySize,
                         GEMM_SMEM);
    cudaFuncSetAttribute(attn_mma, cudaFuncAttributeMaxDynamicSharedMemorySize,
                         ATTN_SMEM);

    // QKV projection: M=8192, N=1536
    tf32_gemm<<<dim3(QKVN / 128, NTOK / 128), 256, GEMM_SMEM>>>(
        x, wqkv, bqkv, nullptr, 0);

    // banded attention
    attn_mma<<<dim3(LL / 64, HH, BB), 128, ATTN_SMEM>>>();

    // out projection: M=8192, N=512
    tf32_gemm<<<dim3(EE / 128, NTOK / 128), 256, GEMM_SMEM>>>(
        nullptr, wout, bout, out, 1);
}

// round 9
// speedup vs baseline: 1.4864x; 1.4864x over previous
#include <cuda_runtime.h>
#include <cuda_fp16.h>
#include <cuda_bf16.h>
#include <cstdint>
#include <math.h>

// Problem constants
#define BB   2
#define LL   4096
#define EE   512
#define HH   8
#define DD   64
#define WIN  128
#define NTOK (BB*LL)          // 8192
#define QKVN (3*EE)           // 1536

// ---------------------------------------------------------------------------
// Device scratch
// ---------------------------------------------------------------------------
__device__ float g_Q[BB*HH*LL*DD];
__device__ float g_K[BB*HH*LL*DD];
__device__ float g_V[BB*HH*LL*DD];
__device__ float g_O[BB*LL*EE];

// ---------------------------------------------------------------------------
// Helpers
// ---------------------------------------------------------------------------
__device__ __forceinline__ uint32_t f2tf32(float x) {
    uint32_t r;
    asm("cvt.rna.tf32.f32 %0, %1;" : "=r"(r) : "f"(x));
    return r;
}

__device__ __forceinline__ void mma_tf32(float* d, const uint32_t* a,
                                         const uint32_t* b) {
    asm volatile(
        "mma.sync.aligned.m16n8k8.row.col.f32.tf32.tf32.f32 "
        "{%0,%1,%2,%3}, {%4,%5,%6,%7}, {%8,%9}, {%0,%1,%2,%3};"
        : "+f"(d[0]), "+f"(d[1]), "+f"(d[2]), "+f"(d[3])
        : "r"(a[0]), "r"(a[1]), "r"(a[2]), "r"(a[3]),
          "r"(b[0]), "r"(b[1]));
}

__device__ __forceinline__ void mma_f16(float* d, const uint32_t* a,
                                        const uint32_t* b) {
    asm volatile(
        "mma.sync.aligned.m16n8k16.row.col.f32.f16.f16.f32 "
        "{%0,%1,%2,%3}, {%4,%5,%6,%7}, {%8,%9}, {%0,%1,%2,%3};"
        : "+f"(d[0]), "+f"(d[1]), "+f"(d[2]), "+f"(d[3])
        : "r"(a[0]), "r"(a[1]), "r"(a[2]), "r"(a[3]),
          "r"(b[0]), "r"(b[1]));
}

__device__ __forceinline__ uint32_t pack_h2(__half a, __half b) {
    return (uint32_t)__half_as_ushort(a) | ((uint32_t)__half_as_ushort(b) << 16);
}
__device__ __forceinline__ void split_f16(float x, __half& hi, __half& lo) {
    hi = __float2half_rn(x);
    lo = __float2half_rn(x - __half2float(hi));
}

__device__ __forceinline__ uint32_t smem_u32(const void* p) {
    uint32_t a;
    asm("{ .reg .u64 t; cvta.to.shared.u64 t, %1; cvt.u32.u64 %0, t; }"
        : "=r"(a) : "l"(p));
    return a;
}
__device__ __forceinline__ void cp16(uint32_t dst, const void* src) {
    asm volatile("cp.async.ca.shared.global [%0], [%1], 16;"
                 :: "r"(dst), "l"(src));
}
#define CP_COMMIT() asm volatile("cp.async.commit_group;" ::: "memory")

// ---------------------------------------------------------------------------
// tf32 mma.sync GEMM, 3-stage cp.async pipeline, ONE sync per chunk.
//   C[M,N] = A[M,K] @ Bw[N,K]^T + bias, K = 512.
//   CTA tile 128x128, BK=32, 8 warps, warp tile 64x32.
// ---------------------------------------------------------------------------
#define SPAD 36
#define GSZ  (128 * SPAD)
#define GEMM_SMEM (6 * GSZ * 4)     // A0 A1 A2 | B0 B1 B2

__global__ __launch_bounds__(256) void tf32_gemm(
    const float* __restrict__ Ain, const float* __restrict__ Bw,
    const float* __restrict__ bias, float* __restrict__ outp, int mode)
{
    extern __shared__ float smg[];
    const uint32_t sbase = smem_u32(smg);

    const int tid = threadIdx.x;
    const int m0 = blockIdx.y * 128;
    const int n0 = blockIdx.x * 128;
    const float* A = (mode == 1) ? g_O : Ain;

    const int w    = tid >> 5;
    const int lane = tid & 31;
    const int g    = lane >> 2;
    const int c    = lane & 3;
    const int rm   = (w >> 2) * 64;
    const int cn   = (w & 3) * 32;

    float acc[4][4][4];
    #pragma unroll
    for (int mi = 0; mi < 4; mi++)
        #pragma unroll
        for (int ni = 0; ni < 4; ni++)
            #pragma unroll
            for (int r = 0; r < 4; r++) acc[mi][ni][r] = 0.f;

    const int lrow = tid >> 3;
    const int lk4  = (tid & 7) * 4;

    auto issue_chunk = [&](int kc, int p) {
        const float* Ag = A  + (size_t)m0 * EE + kc * 32;
        const float* Bg = Bw + (size_t)n0 * EE + kc * 32;
        #pragma unroll
        for (int i = 0; i < 4; i++) {
            int row = lrow + i * 32;
            cp16(sbase + (uint32_t)((p * GSZ + row * SPAD + lk4) * 4),
                 Ag + (size_t)row * EE + lk4);
            cp16(sbase + (uint32_t)(((3 + p) * GSZ + row * SPAD + lk4) * 4),
                 Bg + (size_t)row * EE + lk4);
        }
    };

    issue_chunk(0, 0); CP_COMMIT();
    issue_chunk(1, 1); CP_COMMIT();

    for (int kc = 0; kc < 16; kc++) {
        const int p = kc % 3;
        if (kc < 15) asm volatile("cp.async.wait_group 1;" ::: "memory");
        else         asm volatile("cp.async.wait_group 0;" ::: "memory");
        __syncthreads();

        if (kc + 2 < 16) {
            issue_chunk(kc + 2, (kc + 2) % 3);
            CP_COMMIT();
        }

        const float* Asp = smg + p * GSZ;
        const float* Bsp = smg + (3 + p) * GSZ;

        #pragma unroll
        for (int ks = 0; ks < 4; ks++) {
            uint32_t af[4][4], bf[4][2];
            #pragma unroll
            for (int mi = 0; mi < 4; mi++) {
                const float* base = Asp + (rm + mi * 16 + g) * SPAD + ks * 8;
                af[mi][0] = f2tf32(base[c]);
                af[mi][1] = f2tf32(base[8 * SPAD + c]);
                af[mi][2] = f2tf32(base[c + 4]);
                af[mi][3] = f2tf32(base[8 * SPAD + c + 4]);
            }
            #pragma unroll
            for (int ni = 0; ni < 4; ni++) {
                const float* base = Bsp + (cn + ni * 8 + g) * SPAD + ks * 8;
                bf[ni][0] = f2tf32(base[c]);
                bf[ni][1] = f2tf32(base[c + 4]);
            }
            #pragma unroll
            for (int mi = 0; mi < 4; mi++)
                #pragma unroll
                for (int ni = 0; ni < 4; ni++)
                    mma_tf32(acc[mi][ni], af[mi], bf[ni]);
        }
        // no trailing sync: next iteration's sync protects buffer reuse
    }

    float bv[4][2];
    #pragma unroll
    for (int ni = 0; ni < 4; ni++) {
        int gn = n0 + cn + ni * 8 + 2 * c;
        bv[ni][0] = bias[gn];
        bv[ni][1] = bias[gn + 1];
    }

    if (mode == 0) {
        const int gnb = n0 + cn;
        const int sel = gnb >> 9;
        const int h   = (gnb >> 6) & 7;
        const float scale = (sel == 0) ? 0.125f : 1.0f;
        float* dst = (sel == 0) ? g_Q : (sel == 1) ? g_K : g_V;
        #pragma unroll
        for (int mi = 0; mi < 4; mi++) {
            #pragma unroll
            for (int half = 0; half < 2; half++) {
                int gm  = m0 + rm + mi * 16 + g + half * 8;
                int bat = gm >> 12;
                int l   = gm & (LL - 1);
                size_t rowbase = (((size_t)(bat * HH + h) * LL) + l) * DD;
                #pragma unroll
                for (int ni = 0; ni < 4; ni++) {
                    int gn = n0 + cn + ni * 8 + 2 * c;
                    int d  = gn & 63;
                    float2 o;
                    o.x = (acc[mi][ni][half * 2 + 0] + bv[ni][0]) * scale;
                    o.y = (acc[mi][ni][half * 2 + 1] + bv[ni][1]) * scale;
                    *reinterpret_cast<float2*>(dst + rowbase + d) = o;
                }
            }
        }
    } else {
        #pragma unroll
        for (int mi = 0; mi < 4; mi++) {
            #pragma unroll
            for (int half = 0; half < 2; half++) {
                int gm = m0 + rm + mi * 16 + g + half * 8;
                #pragma unroll
                for (int ni = 0; ni < 4; ni++) {
                    int gn = n0 + cn + ni * 8 + 2 * c;
                    float2 o;
                    o.x = acc[mi][ni][half * 2 + 0] + bv[ni][0];
                    o.y = acc[mi][ni][half * 2 + 1] + bv[ni][1];
                    *reinterpret_cast<float2*>(outp + (size_t)gm * EE + gn) = o;
                }
            }
        }
    }
}

// ---------------------------------------------------------------------------
// Banded flash attention, fp16 m16n8k16 MMA.
//   Q, P: hi/lo fp16 split (error ~2^-22). K, V: single fp16 (~2^-12 rms).
//   Planes (half, pitch 72): Qh | Ql | Ks | Vt (transposed) | Ph | Pl.
//   54 KB smem -> 4 CTAs/SM. All fragment LDS conflict-free
//   (pitch/2 = 36 ≡ 4 mod 32 -> bank = 4g + c).
// ---------------------------------------------------------------------------
#define AP 72
#define HPL (64 * AP)               // halves per plane
#define ATTN_SMEM (6 * HPL * 2)

__global__ __launch_bounds__(128, 4) void attn_mma()
{
    extern __shared__ __half smh[];
    __half* Qh = smh;
    __half* Ql = smh + 1 * HPL;
    __half* Ks = smh + 2 * HPL;
    __half* Vt = smh + 3 * HPL;
    __half* Ph = smh + 4 * HPL;
    __half* Pl = smh + 5 * HPL;

    const int q0 = blockIdx.x * 64;
    const int h  = blockIdx.y;
    const int b  = blockIdx.z;
    const int tid  = threadIdx.x;
    const int w    = tid >> 5;
    const int lane = tid & 31;
    const int g    = lane >> 2;
    const int c    = lane & 3;

    const size_t head_off = ((size_t)(b * HH + h) * LL) * DD;
    const float* Qg = g_Q + head_off;
    const float* Kg = g_K + head_off;
    const float* Vg = g_V + head_off;

    // ---- load Q tile [64][64], split hi/lo once ----
    #pragma unroll
    for (int i = 0; i < 8; i++) {
        int u = tid + i * 128;
        int row = u >> 4;
        int col = (u & 15) * 4;
        float4 v = *reinterpret_cast<const float4*>(&Qg[(size_t)(q0 + row) * DD + col]);
        __half hx, lx, hy, ly, hz, lz, hw, lw;
        split_f16(v.x, hx, lx); split_f16(v.y, hy, ly);
        split_f16(v.z, hz, lz); split_f16(v.w, hw, lw);
        uint32_t* qh = reinterpret_cast<uint32_t*>(&Qh[row * AP + col]);
        qh[0] = pack_h2(hx, hy); qh[1] = pack_h2(hz, hw);
        uint32_t* ql = reinterpret_cast<uint32_t*>(&Ql[row * AP + col]);
        ql[0] = pack_h2(lx, ly); ql[1] = pack_h2(lz, lw);
    }

    float om[2] = {-1e30f, -1e30f};
    float ol[2] = {0.f, 0.f};
    float oacc[8][4];
    #pragma unroll
    for (int nt = 0; nt < 8; nt++)
        #pragma unroll
        for (int r = 0; r < 4; r++) oacc[nt][r] = 0.f;

    __syncthreads();

    const int row_lo = 16 * w + g;
    const int q_lo = q0 + row_lo;
    const int q_hi = q_lo + 8;

    for (int ch = 0; ch < 5; ch++) {
        const int kcc = q0 - 128 + ch * 64;
        if (kcc + 64 <= 0 || kcc >= LL) continue;

        // ---- stage K (natural) and V (transposed), fp16 ----
        #pragma unroll
        for (int i = 0; i < 8; i++) {
            int u = tid + i * 128;
            int row = u >> 4;             // key_local
            int col = (u & 15) * 4;       // d
            int key = kcc + row;
            int kk = min(max(key, 0), LL - 1);
            float4 kv = *reinterpret_cast<const float4*>(&Kg[(size_t)kk * DD + col]);
            uint32_t* kp = reinterpret_cast<uint32_t*>(&Ks[row * AP + col]);
            kp[0] = pack_h2(__float2half_rn(kv.x), __float2half_rn(kv.y));
            kp[1] = pack_h2(__float2half_rn(kv.z), __float2half_rn(kv.w));
            float4 vv = *reinterpret_cast<const float4*>(&Vg[(size_t)kk * DD + col]);
            Vt[(col + 0) * AP + row] = __float2half_rn(vv.x);
            Vt[(col + 1) * AP + row] = __float2half_rn(vv.y);
            Vt[(col + 2) * AP + row] = __float2half_rn(vv.z);
            Vt[(col + 3) * AP + row] = __float2half_rn(vv.w);
        }
        __syncthreads();

        // ---- scores: (Qh + Ql) @ K^T, fp16 k16 ----
        float sacc[8][4];
        #pragma unroll
        for (int nt = 0; nt < 8; nt++)
            #pragma unroll
            for (int r = 0; r < 4; r++) sacc[nt][r] = 0.f;

        #pragma unroll
        for (int ks = 0; ks < 4; ks++) {
            const int ab = row_lo * AP + ks * 16 + 2 * c;
            uint32_t ah[4], al[4];
            ah[0] = *reinterpret_cast<const uint32_t*>(&Qh[ab]);
            ah[1] = *reinterpret_cast<const uint32_t*>(&Qh[ab + 8 * AP]);
            ah[2] = *reinterpret_cast<const uint32_t*>(&Qh[ab + 8]);
            ah[3] = *reinterpret_cast<const uint32_t*>(&Qh[ab + 8 * AP + 8]);
            al[0] = *reinterpret_cast<const uint32_t*>(&Ql[ab]);
            al[1] = *reinterpret_cast<const uint32_t*>(&Ql[ab + 8 * AP]);
            al[2] = *reinterpret_cast<const uint32_t*>(&Ql[ab + 8]);
            al[3] = *reinterpret_cast<const uint32_t*>(&Ql[ab + 8 * AP + 8]);
            #pragma unroll
            for (int nt = 0; nt < 8; nt++) {
                const int bb = (nt * 8 + g) * AP + ks * 16 + 2 * c;
                uint32_t bf[2];
                bf[0] = *reinterpret_cast<const uint32_t*>(&Ks[bb]);
                bf[1] = *reinterpret_cast<const uint32_t*>(&Ks[bb + 8]);
                mma_f16(sacc[nt], ah, bf);
                mma_f16(sacc[nt], al, bf);
            }
        }

        // ---- mask ----
        #pragma unroll
        for (int nt = 0; nt < 8; nt++) {
            #pragma unroll
            for (int r = 0; r < 4; r++) {
                int key = kcc + nt * 8 + 2 * c + (r & 1);
                int q   = (r >> 1) ? q_hi : q_lo;
                int dlt = q - key;
                bool ok = (key >= 0) && (key < LL) && (dlt != 0) &&
                          (dlt <= WIN) && (dlt >= -WIN);
                if (!ok) sacc[nt][r] = -1e30f;
            }
        }

        // ---- online softmax; write P (hi/lo fp16) ----
        float mx0 = -1e30f, mx1 = -1e30f;
        #pragma unroll
        for (int nt = 0; nt < 8; nt++) {
            mx0 = fmaxf(mx0, fmaxf(sacc[nt][0], sacc[nt][1]));
            mx1 = fmaxf(mx1, fmaxf(sacc[nt][2], sacc[nt][3]));
        }
        mx0 = fmaxf(mx0, __shfl_xor_sync(0xffffffffu, mx0, 1));
        mx0 = fmaxf(mx0, __shfl_xor_sync(0xffffffffu, mx0, 2));
        mx1 = fmaxf(mx1, __shfl_xor_sync(0xffffffffu, mx1, 1));
        mx1 = fmaxf(mx1, __shfl_xor_sync(0xffffffffu, mx1, 2));

        float m0n = fmaxf(om[0], mx0);
        float m1n = fmaxf(om[1], mx1);
        float alpha0 = __expf(om[0] - m0n);
        float alpha1 = __expf(om[1] - m1n);

        float sum0 = 0.f, sum1 = 0.f;
        #pragma unroll
        for (int nt = 0; nt < 8; nt++) {
            float p0 = __expf(sacc[nt][0] - m0n);
            float p1 = __expf(sacc[nt][1] - m0n);
            float p2 = __expf(sacc[nt][2] - m1n);
            float p3 = __expf(sacc[nt][3] - m1n);
            sum0 += p0 + p1;
            sum1 += p2 + p3;
            __half h0, l0, h1, l1, h2, l2, h3, l3;
            split_f16(p0, h0, l0); split_f16(p1, h1, l1);
            split_f16(p2, h2, l2); split_f16(p3, h3, l3);
            const int pi_lo = row_lo * AP + nt * 8 + 2 * c;
            const int pi_hi = pi_lo + 8 * AP;
            *reinterpret_cast<uint32_t*>(&Ph[pi_lo]) = pack_h2(h0, h1);
            *reinterpret_cast<uint32_t*>(&Pl[pi_lo]) = pack_h2(l0, l1);
            *reinterpret_cast<uint32_t*>(&Ph[pi_hi]) = pack_h2(h2, h3);
            *reinterpret_cast<uint32_t*>(&Pl[pi_hi]) = pack_h2(l2, l3);
        }
        sum0 += __shfl_xor_sync(0xffffffffu, sum0, 1);
        sum0 += __shfl_xor_sync(0xffffffffu, sum0, 2);
        sum1 += __shfl_xor_sync(0xffffffffu, sum1, 1);
        sum1 += __shfl_xor_sync(0xffffffffu, sum1, 2);

        ol[0] = ol[0] * alpha0 + sum0;
        ol[1] = ol[1] * alpha1 + sum1;
        om[0] = m0n;
        om[1] = m1n;

        #pragma unroll
        for (int nt = 0; nt < 8; nt++) {
            oacc[nt][0] *= alpha0;
            oacc[nt][1] *= alpha0;
            oacc[nt][2] *= alpha1;
            oacc[nt][3] *= alpha1;
        }
        __syncwarp();   // P rows are warp-private

        // ---- O += (Ph + Pl) @ V, fp16 k16 (keys = k-dim) ----
        #pragma unroll
        for (int ks = 0; ks < 4; ks++) {
            const int pb = row_lo * AP + ks * 16 + 2 * c;
            uint32_t ah[4], al[4];
            ah[0] = *reinterpret_cast<const uint32_t*>(&Ph[pb]);
            ah[1] = *reinterpret_cast<const uint32_t*>(&Ph[pb + 8 * AP]);
            ah[2] = *reinterpret_cast<const uint32_t*>(&Ph[pb + 8]);
            ah[3] = *reinterpret_cast<const uint32_t*>(&Ph[pb + 8 * AP + 8]);
            al[0] = *reinterpret_cast<const uint32_t*>(&Pl[pb]);
            al[1] = *reinterpret_cast<const uint32_t*>(&Pl[pb + 8 * AP]);
            al[2] = *reinterpret_cast<const uint32_t*>(&Pl[pb + 8]);
            al[3] = *reinterpret_cast<const uint32_t*>(&Pl[pb + 8 * AP + 8]);
            #pragma unroll
            for (int nt = 0; nt < 8; nt++) {
                const int vb = (nt * 8 + g) * AP + ks * 16 + 2 * c;
                uint32_t bf[2];
                bf[0] = *reinterpret_cast<const uint32_t*>(&Vt[vb]);
                bf[1] = *reinterpret_cast<const uint32_t*>(&Vt[vb + 8]);
                mma_f16(oacc[nt], ah, bf);
                mma_f16(oacc[nt], al, bf);
            }
        }
        __syncthreads();   // protect Ks/Vt before next chunk staging
    }

    // ---- epilogue ----
    const float inv0 = 1.f / ol[0];
    const float inv1 = 1.f / ol[1];
    const size_t base_lo = ((size_t)(b * LL + q_lo) * HH + h) * DD;
    const size_t base_hi = ((size_t)(b * LL + q_hi) * HH + h) * DD;
    #pragma unroll
    for (int nt = 0; nt < 8; nt++) {
        int d = nt * 8 + 2 * c;
        *reinterpret_cast<float2*>(&g_O[base_lo + d]) =
            make_float2(oacc[nt][0] * inv0, oacc[nt][1] * inv0);
        *reinterpret_cast<float2*>(&g_O[base_hi + d]) =
            make_float2(oacc[nt][2] * inv1, oacc[nt][3] * inv1);
    }
}

// ---------------------------------------------------------------------------
// Entry point
// ---------------------------------------------------------------------------
extern "C" void kernel_launch(void* const* d_in, const int* in_sizes, int n_in,
                              void* d_out, int out_size)
{
    const float* x    = (const float*)d_in[0];   // [B,L,E]
    const float* wqkv = (const float*)d_in[1];   // [3E,E]
    const float* bqkv = (const float*)d_in[2];   // [3E]
    const float* wout = (const float*)d_in[3];   // [E,E]
    const float* bout = (const float*)d_in[4];   // [E]
    float* out = (float*)d_out;                  // [B,L,E]

    (void)in_sizes; (void)n_in; (void)out_size;

    cudaFuncSetAttribute(tf32_gemm, cudaFuncAttributeMaxDynamicSharedMemorySize,
                         GEMM_SMEM);
    cudaFuncSetAttribute(attn_mma, cudaFuncAttributeMaxDynamicSharedMemorySize,
                         ATTN_SMEM);

    // QKV projection: M=8192, N=1536
    tf32_gemm<<<dim3(QKVN / 128, NTOK / 128), 256, GEMM_SMEM>>>(
        x, wqkv, bqkv, nullptr, 0);

    // banded attention (fp16 tensor path)
    attn_mma<<<dim3(LL / 64, HH, BB), 128, ATTN_SMEM>>>();

    // out projection: M=8192, N=512
    tf32_gemm<<<dim3(EE / 128, NTOK / 128), 256, GEMM_SMEM>>>(
        nullptr, wout, bout, out, 1);
}

// round 10
// speedup vs baseline: 1.7012x; 1.1445x over previous
#include <cuda_runtime.h>
#include <cuda_fp16.h>
#include <cstdint>
#include <math.h>

// Problem constants
#define BB   2
#define LL   4096
#define EE   512
#define HH   8
#define DD   64
#define WIN  128
#define NTOK (BB*LL)          // 8192
#define QKVN (3*EE)           // 1536

// ---------------------------------------------------------------------------
// Device scratch (half precision dataflow)
// ---------------------------------------------------------------------------
__device__ __half g_Xh[NTOK*EE], g_Xl[NTOK*EE];      // x split hi/lo
__device__ __half g_Wq[QKVN*EE];                      // qkv weights (rounded)
__device__ __half g_Wo[EE*EE];                        // out weights (rounded)
__device__ __half g_Qh[BB*HH*LL*DD], g_Ql[BB*HH*LL*DD];
__device__ __half g_Kh[BB*HH*LL*DD];                  // K single half [B,H,L,D]
__device__ __half g_Vt[BB*HH*DD*LL];                  // V transposed [B,H,D,L]
__device__ __half g_Oh[BB*LL*EE], g_Ol[BB*LL*EE];     // attn out split

// ---------------------------------------------------------------------------
// Helpers
// ---------------------------------------------------------------------------
__device__ __forceinline__ void mma_f16(float* d, const uint32_t* a,
                                        const uint32_t* b) {
    asm volatile(
        "mma.sync.aligned.m16n8k16.row.col.f32.f16.f16.f32 "
        "{%0,%1,%2,%3}, {%4,%5,%6,%7}, {%8,%9}, {%0,%1,%2,%3};"
        : "+f"(d[0]), "+f"(d[1]), "+f"(d[2]), "+f"(d[3])
        : "r"(a[0]), "r"(a[1]), "r"(a[2]), "r"(a[3]),
          "r"(b[0]), "r"(b[1]));
}

__device__ __forceinline__ uint32_t pack_h2(__half a, __half b) {
    return (uint32_t)__half_as_ushort(a) | ((uint32_t)__half_as_ushort(b) << 16);
}
__device__ __forceinline__ void split_f16(float x, __half& hi, __half& lo) {
    hi = __float2half_rn(x);
    lo = __float2half_rn(x - __half2float(hi));
}

__device__ __forceinline__ uint32_t smem_u32(const void* p) {
    uint32_t a;
    asm("{ .reg .u64 t; cvta.to.shared.u64 t, %1; cvt.u32.u64 %0, t; }"
        : "=r"(a) : "l"(p));
    return a;
}
__device__ __forceinline__ void cp16(uint32_t dst, const void* src) {
    asm volatile("cp.async.ca.shared.global [%0], [%1], 16;"
                 :: "r"(dst), "l"(src));
}
#define CP_COMMIT() asm volatile("cp.async.commit_group;" ::: "memory")

// ---------------------------------------------------------------------------
// Prep kernels: split x to hi/lo halves; round weights to half.
// ---------------------------------------------------------------------------
__global__ __launch_bounds__(256) void prep_split_x(const float* __restrict__ x)
{
    int i = (blockIdx.x * 256 + threadIdx.x) * 4;
    float4 v = *reinterpret_cast<const float4*>(&x[i]);
    __half h0, l0, h1, l1, h2, l2, h3, l3;
    split_f16(v.x, h0, l0); split_f16(v.y, h1, l1);
    split_f16(v.z, h2, l2); split_f16(v.w, h3, l3);
    uint2 uh; uh.x = pack_h2(h0, h1); uh.y = pack_h2(h2, h3);
    uint2 ul; ul.x = pack_h2(l0, l1); ul.y = pack_h2(l2, l3);
    *reinterpret_cast<uint2*>(&g_Xh[i]) = uh;
    *reinterpret_cast<uint2*>(&g_Xl[i]) = ul;
}

__global__ __launch_bounds__(256) void prep_round(const float* __restrict__ w,
                                                  int which)
{
    __half* dst = which ? g_Wo : g_Wq;
    int i = (blockIdx.x * 256 + threadIdx.x) * 4;
    float4 v = *reinterpret_cast<const float4*>(&w[i]);
    uint2 u;
    u.x = pack_h2(__float2half_rn(v.x), __float2half_rn(v.y));
    u.y = pack_h2(__float2half_rn(v.z), __float2half_rn(v.w));
    *reinterpret_cast<uint2*>(&dst[i]) = u;
}

// ---------------------------------------------------------------------------
// fp16 m16n8k16 GEMM: C = (Ah+Al)[M,K] @ Bh[N,K]^T + bias, K=512.
//   CTA 128x128, BK=32, 8 warps, warp tile 64x32. 3-stage cp.async pipeline.
//   mode 0: A = Xh/Xl, B = Wq -> scatter Qh/Ql (x0.125), Kh, Vt epilogues
//   mode 1: A = Oh/Ol, B = Wo -> f32 out + bias
//   Smem plane pitch 40 halves (20 words ≡ 20 mod 32): fragment banks
//   20g + c all distinct mod 32 -> conflict-free.
// ---------------------------------------------------------------------------
#define HP   40
#define PLH  (128 * HP)                 // halves per plane
#define GEMM_SMEM (9 * PLH * 2)         // 3 stages x (Ah | Al | Bh)

__global__ __launch_bounds__(256) void fp16_gemm(
    const float* __restrict__ bias, float* __restrict__ outp, int mode)
{
    extern __shared__ __half smh[];
    const uint32_t sbase = smem_u32(smh);

    const int tid = threadIdx.x;
    const int m0 = blockIdx.y * 128;
    const int n0 = blockIdx.x * 128;

    const __half* Ahg = mode ? g_Oh : g_Xh;
    const __half* Alg = mode ? g_Ol : g_Xl;
    const __half* Bg  = mode ? g_Wo : g_Wq;

    const int w    = tid >> 5;
    const int lane = tid & 31;
    const int g    = lane >> 2;
    const int c    = lane & 3;
    const int rm   = (w >> 2) * 64;
    const int cn   = (w & 3) * 32;

    float acc[4][4][4];
    #pragma unroll
    for (int mi = 0; mi < 4; mi++)
        #pragma unroll
        for (int ni = 0; ni < 4; ni++)
            #pragma unroll
            for (int r = 0; r < 4; r++) acc[mi][ni][r] = 0.f;

    const int lrow = tid >> 2;          // 0..63
    const int seg  = (tid & 3) * 8;     // half offset within 32-half row chunk

    auto issue_chunk = [&](int kc, int p) {
        const __half* a = Ahg + (size_t)m0 * EE + kc * 32;
        const __half* l = Alg + (size_t)m0 * EE + kc * 32;
        const __half* bb = Bg + (size_t)n0 * EE + kc * 32;
        const uint32_t sb = sbase + (uint32_t)(p * 3 * PLH * 2);
        #pragma unroll
        for (int i = 0; i < 2; i++) {
            int row = lrow + i * 64;
            uint32_t so = (uint32_t)((row * HP + seg) * 2);
            cp16(sb + so,               a  + (size_t)row * EE + seg);
            cp16(sb + PLH * 2 + so,     l  + (size_t)row * EE + seg);
            cp16(sb + 2 * PLH * 2 + so, bb + (size_t)row * EE + seg);
        }
    };

    issue_chunk(0, 0); CP_COMMIT();
    issue_chunk(1, 1); CP_COMMIT();

    for (int kc = 0; kc < 16; kc++) {
        const int p = kc % 3;
        if (kc < 15) asm volatile("cp.async.wait_group 1;" ::: "memory");
        else         asm volatile("cp.async.wait_group 0;" ::: "memory");
        __syncthreads();

        if (kc + 2 < 16) {
            issue_chunk(kc + 2, (kc + 2) % 3);
            CP_COMMIT();
        }

        const __half* Asp = smh + p * 3 * PLH;
        const __half* Alp = Asp + PLH;
        const __half* Bsp = Asp + 2 * PLH;

        #pragma unroll
        for (int ks = 0; ks < 2; ks++) {
            const int ko = ks * 16 + 2 * c;
            uint32_t ah[4][4], al[4][4], bf[4][2];
            #pragma unroll
            for (int mi = 0; mi < 4; mi++) {
                const int ab = (rm + mi * 16 + g) * HP + ko;
                ah[mi][0] = *reinterpret_cast<const uint32_t*>(&Asp[ab]);
                ah[mi][1] = *reinterpret_cast<const uint32_t*>(&Asp[ab + 8 * HP]);
                ah[mi][2] = *reinterpret_cast<const uint32_t*>(&Asp[ab + 8]);
                ah[mi][3] = *reinterpret_cast<const uint32_t*>(&Asp[ab + 8 * HP + 8]);
                al[mi][0] = *reinterpret_cast<const uint32_t*>(&Alp[ab]);
                al[mi][1] = *reinterpret_cast<const uint32_t*>(&Alp[ab + 8 * HP]);
                al[mi][2] = *reinterpret_cast<const uint32_t*>(&Alp[ab + 8]);
                al[mi][3] = *reinterpret_cast<const uint32_t*>(&Alp[ab + 8 * HP + 8]);
            }
            #pragma unroll
            for (int ni = 0; ni < 4; ni++) {
                const int bb = (cn + ni * 8 + g) * HP + ko;
                bf[ni][0] = *reinterpret_cast<const uint32_t*>(&Bsp[bb]);
                bf[ni][1] = *reinterpret_cast<const uint32_t*>(&Bsp[bb + 8]);
            }
            #pragma unroll
            for (int mi = 0; mi < 4; mi++)
                #pragma unroll
                for (int ni = 0; ni < 4; ni++) {
                    mma_f16(acc[mi][ni], ah[mi], bf[ni]);
                    mma_f16(acc[mi][ni], al[mi], bf[ni]);
                }
        }
    }

    float bv[4][2];
    #pragma unroll
    for (int ni = 0; ni < 4; ni++) {
        int gn = n0 + cn + ni * 8 + 2 * c;
        bv[ni][0] = bias[gn];
        bv[ni][1] = bias[gn + 1];
    }

    if (mode == 0) {
        const int gnb = n0 + cn;
        const int sel = gnb >> 9;                  // 0=Q 1=K 2=V
        const int h   = (gnb >> 6) & 7;
        #pragma unroll
        for (int mi = 0; mi < 4; mi++) {
            #pragma unroll
            for (int half = 0; half < 2; half++) {
                int gm  = m0 + rm + mi * 16 + g + half * 8;
                int bat = gm >> 12;
                int l   = gm & (LL - 1);
                #pragma unroll
                for (int ni = 0; ni < 4; ni++) {
                    int gn = n0 + cn + ni * 8 + 2 * c;
                    int d  = gn & 63;
                    float f0 = acc[mi][ni][half * 2 + 0] + bv[ni][0];
                    float f1 = acc[mi][ni][half * 2 + 1] + bv[ni][1];
                    if (sel == 0) {
                        f0 *= 0.125f; f1 *= 0.125f;
                        size_t rb = (((size_t)(bat * HH + h) * LL) + l) * DD + d;
                        __half h0, l0, h1, l1;
                        split_f16(f0, h0, l0); split_f16(f1, h1, l1);
                        *reinterpret_cast<uint32_t*>(&g_Qh[rb]) = pack_h2(h0, h1);
                        *reinterpret_cast<uint32_t*>(&g_Ql[rb]) = pack_h2(l0, l1);
                    } else if (sel == 1) {
                        size_t rb = (((size_t)(bat * HH + h) * LL) + l) * DD + d;
                        *reinterpret_cast<uint32_t*>(&g_Kh[rb]) =
                            pack_h2(__float2half_rn(f0), __float2half_rn(f1));
                    } else {
                        size_t vb = (((size_t)(bat * HH + h) * DD) + d) * LL + l;
                        g_Vt[vb]      = __float2half_rn(f0);
                        g_Vt[vb + LL] = __float2half_rn(f1);
                    }
                }
            }
        }
    } else {
        #pragma unroll
        for (int mi = 0; mi < 4; mi++) {
            #pragma unroll
            for (int half = 0; half < 2; half++) {
                int gm = m0 + rm + mi * 16 + g + half * 8;
                #pragma unroll
                for (int ni = 0; ni < 4; ni++) {
                    int gn = n0 + cn + ni * 8 + 2 * c;
                    float2 o;
                    o.x = acc[mi][ni][half * 2 + 0] + bv[ni][0];
                    o.y = acc[mi][ni][half * 2 + 1] + bv[ni][1];
                    *reinterpret_cast<float2*>(&outp[(size_t)gm * EE + gn]) = o;
                }
            }
        }
    }
}

// ---------------------------------------------------------------------------
// Banded flash attention, fp16 m16n8k16 MMA, pure-copy staging.
//   Planes (half, pitch 72): Qh | Ql | Ks | Vt | Ph | Pl. 54 KB -> 4 CTAs/SM.
// ---------------------------------------------------------------------------
#define AP 72
#define HPL (64 * AP)
#define ATTN_SMEM (6 * HPL * 2)

__global__ __launch_bounds__(128, 4) void attn_mma()
{
    extern __shared__ __half smq[];
    __half* Qs = smq;
    __half* Ql = smq + 1 * HPL;
    __half* Ks = smq + 2 * HPL;
    __half* Vt = smq + 3 * HPL;
    __half* Ph = smq + 4 * HPL;
    __half* Pl = smq + 5 * HPL;

    const int q0 = blockIdx.x * 64;
    const int h  = blockIdx.y;
    const int b  = blockIdx.z;
    const int tid  = threadIdx.x;
    const int w    = tid >> 5;
    const int lane = tid & 31;
    const int g    = lane >> 2;
    const int c    = lane & 3;

    const size_t khead = ((size_t)(b * HH + h) * LL) * DD;
    const size_t vhead = ((size_t)(b * HH + h) * DD) * LL;

    // ---- stage Q planes (pure copy) ----
    #pragma unroll
    for (int i = 0; i < 4; i++) {
        int u = tid + i * 128;
        int row = u >> 3;
        int seg = (u & 7) * 8;
        *reinterpret_cast<uint4*>(&Qs[row * AP + seg]) =
            *reinterpret_cast<const uint4*>(&g_Qh[khead + (size_t)(q0 + row) * DD + seg]);
        *reinterpret_cast<uint4*>(&Ql[row * AP + seg]) =
            *reinterpret_cast<const uint4*>(&g_Ql[khead + (size_t)(q0 + row) * DD + seg]);
    }

    float om[2] = {-1e30f, -1e30f};
    float ol[2] = {0.f, 0.f};
    float oacc[8][4];
    #pragma unroll
    for (int nt = 0; nt < 8; nt++)
        #pragma unroll
        for (int r = 0; r < 4; r++) oacc[nt][r] = 0.f;

    __syncthreads();

    const int row_lo = 16 * w + g;
    const int q_lo = q0 + row_lo;
    const int q_hi = q_lo + 8;

    for (int ch = 0; ch < 5; ch++) {
        const int kcc = q0 - 128 + ch * 64;
        if (kcc + 64 <= 0 || kcc >= LL) continue;

        // ---- stage K (natural) and V (pre-transposed) — pure copies ----
        #pragma unroll
        for (int i = 0; i < 4; i++) {
            int u = tid + i * 128;
            int row = u >> 3;
            int seg = (u & 7) * 8;
            int kk = min(max(kcc + row, 0), LL - 1);
            *reinterpret_cast<uint4*>(&Ks[row * AP + seg]) =
                *reinterpret_cast<const uint4*>(&g_Kh[khead + (size_t)kk * DD + seg]);
            int kb = min(max(kcc + seg, 0), LL - 8);
            *reinterpret_cast<uint4*>(&Vt[row * AP + seg]) =
                *reinterpret_cast<const uint4*>(&g_Vt[vhead + (size_t)row * LL + kb]);
        }
        __syncthreads();

        // ---- scores: (Qh + Ql) @ K^T ----
        float sacc[8][4];
        #pragma unroll
        for (int nt = 0; nt < 8; nt++)
            #pragma unroll
            for (int r = 0; r < 4; r++) sacc[nt][r] = 0.f;

        #pragma unroll
        for (int ks = 0; ks < 4; ks++) {
            const int ab = row_lo * AP + ks * 16 + 2 * c;
            uint32_t ah[4], al[4];
            ah[0] = *reinterpret_cast<const uint32_t*>(&Qs[ab]);
            ah[1] = *reinterpret_cast<const uint32_t*>(&Qs[ab + 8 * AP]);
            ah[2] = *reinterpret_cast<const uint32_t*>(&Qs[ab + 8]);
            ah[3] = *reinterpret_cast<const uint32_t*>(&Qs[ab + 8 * AP + 8]);
            al[0] = *reinterpret_cast<const uint32_t*>(&Ql[ab]);
            al[1] = *reinterpret_cast<const uint32_t*>(&Ql[ab + 8 * AP]);
            al[2] = *reinterpret_cast<const uint32_t*>(&Ql[ab + 8]);
            al[3] = *reinterpret_cast<const uint32_t*>(&Ql[ab + 8 * AP + 8]);
            #pragma unroll
            for (int nt = 0; nt < 8; nt++) {
                const int bb = (nt * 8 + g) * AP + ks * 16 + 2 * c;
                uint32_t bf[2];
                bf[0] = *reinterpret_cast<const uint32_t*>(&Ks[bb]);
                bf[1] = *reinterpret_cast<const uint32_t*>(&Ks[bb + 8]);
                mma_f16(sacc[nt], ah, bf);
                mma_f16(sacc[nt], al, bf);
            }
        }

        // ---- mask ----
        #pragma unroll
        for (int nt = 0; nt < 8; nt++) {
            #pragma unroll
            for (int r = 0; r < 4; r++) {
                int key = kcc + nt * 8 + 2 * c + (r & 1);
                int q   = (r >> 1) ? q_hi : q_lo;
                int dlt = q - key;
                bool ok = (key >= 0) && (key < LL) && (dlt != 0) &&
                          (dlt <= WIN) && (dlt >= -WIN);
                if (!ok) sacc[nt][r] = -1e30f;
            }
        }

        // ---- online softmax; write P hi/lo ----
        float mx0 = -1e30f, mx1 = -1e30f;
        #pragma unroll
        for (int nt = 0; nt < 8; nt++) {
            mx0 = fmaxf(mx0, fmaxf(sacc[nt][0], sacc[nt][1]));
            mx1 = fmaxf(mx1, fmaxf(sacc[nt][2], sacc[nt][3]));
        }
        mx0 = fmaxf(mx0, __shfl_xor_sync(0xffffffffu, mx0, 1));
        mx0 = fmaxf(mx0, __shfl_xor_sync(0xffffffffu, mx0, 2));
        mx1 = fmaxf(mx1, __shfl_xor_sync(0xffffffffu, mx1, 1));
        mx1 = fmaxf(mx1, __shfl_xor_sync(0xffffffffu, mx1, 2));

        float m0n = fmaxf(om[0], mx0);
        float m1n = fmaxf(om[1], mx1);
        float alpha0 = __expf(om[0] - m0n);
        float alpha1 = __expf(om[1] - m1n);

        float sum0 = 0.f, sum1 = 0.f;
        #pragma unroll
        for (int nt = 0; nt < 8; nt++) {
            float p0 = __expf(sacc[nt][0] - m0n);
            float p1 = __expf(sacc[nt][1] - m0n);
            float p2 = __expf(sacc[nt][2] - m1n);
            float p3 = __expf(sacc[nt][3] - m1n);
            sum0 += p0 + p1;
            sum1 += p2 + p3;
            __half h0, l0, h1, l1, h2, l2, h3, l3;
            split_f16(p0, h0, l0); split_f16(p1, h1, l1);
            split_f16(p2, h2, l2); split_f16(p3, h3, l3);
            const int pi_lo = row_lo * AP + nt * 8 + 2 * c;
            const int pi_hi = pi_lo + 8 * AP;
            *reinterpret_cast<uint32_t*>(&Ph[pi_lo]) = pack_h2(h0, h1);
            *reinterpret_cast<uint32_t*>(&Pl[pi_lo]) = pack_h2(l0, l1);
            *reinterpret_cast<uint32_t*>(&Ph[pi_hi]) = pack_h2(h2, h3);
            *reinterpret_cast<uint32_t*>(&Pl[pi_hi]) = pack_h2(l2, l3);
        }
        sum0 += __shfl_xor_sync(0xffffffffu, sum0, 1);
        sum0 += __shfl_xor_sync(0xffffffffu, sum0, 2);
        sum1 += __shfl_xor_sync(0xffffffffu, sum1, 1);
        sum1 += __shfl_xor_sync(0xffffffffu, sum1, 2);

        ol[0] = ol[0] * alpha0 + sum0;
        ol[1] = ol[1] * alpha1 + sum1;
        om[0] = m0n;
        om[1] = m1n;

        #pragma unroll
        for (int nt = 0; nt < 8; nt++) {
            oacc[nt][0] *= alpha0;
            oacc[nt][1] *= alpha0;
            oacc[nt][2] *= alpha1;
            oacc[nt][3] *= alpha1;
        }
        __syncwarp();

        // ---- O += (Ph + Pl) @ V ----
        #pragma unroll
        for (int ks = 0; ks < 4; ks++) {
            const int pb = row_lo * AP + ks * 16 + 2 * c;
            uint32_t ah[4], al[4];
            ah[0] = *reinterpret_cast<const uint32_t*>(&Ph[pb]);
            ah[1] = *reinterpret_cast<const uint32_t*>(&Ph[pb + 8 * AP]);
            ah[2] = *reinterpret_cast<const uint32_t*>(&Ph[pb + 8]);
            ah[3] = *reinterpret_cast<const uint32_t*>(&Ph[pb + 8 * AP + 8]);
            al[0] = *reinterpret_cast<const uint32_t*>(&Pl[pb]);
            al[1] = *reinterpret_cast<const uint32_t*>(&Pl[pb + 8 * AP]);
            al[2] = *reinterpret_cast<const uint32_t*>(&Pl[pb + 8]);
            al[3] = *reinterpret_cast<const uint32_t*>(&Pl[pb + 8 * AP + 8]);
            #pragma unroll
            for (int nt = 0; nt < 8; nt++) {
                const int vb = (nt * 8 + g) * AP + ks * 16 + 2 * c;
                uint32_t bf[2];
                bf[0] = *reinterpret_cast<const uint32_t*>(&Vt[vb]);
                bf[1] = *reinterpret_cast<const uint32_t*>(&Vt[vb + 8]);
                mma_f16(oacc[nt], ah, bf);
                mma_f16(oacc[nt], al, bf);
            }
        }
        __syncthreads();
    }

    // ---- epilogue: normalize, split, write Oh/Ol [B,L,E] ----
    const float inv0 = 1.f / ol[0];
    const float inv1 = 1.f / ol[1];
    const size_t base_lo = ((size_t)(b * LL + q_lo)) * EE + h * DD;
    const size_t base_hi = ((size_t)(b * LL + q_hi)) * EE + h * DD;
    #pragma unroll
    for (int nt = 0; nt < 8; nt++) {
        int d = nt * 8 + 2 * c;
        __half h0, l0, h1, l1;
        split_f16(oacc[nt][0] * inv0, h0, l0);
        split_f16(oacc[nt][1] * inv0, h1, l1);
        *reinterpret_cast<uint32_t*>(&g_Oh[base_lo + d]) = pack_h2(h0, h1);
        *reinterpret_cast<uint32_t*>(&g_Ol[base_lo + d]) = pack_h2(l0, l1);
        split_f16(oacc[nt][2] * inv1, h0, l0);
        split_f16(oacc[nt][3] * inv1, h1, l1);
        *reinterpret_cast<uint32_t*>(&g_Oh[base_hi + d]) = pack_h2(h0, h1);
        *reinterpret_cast<uint32_t*>(&g_Ol[base_hi + d]) = pack_h2(l0, l1);
    }
}

// ---------------------------------------------------------------------------
// Entry point
// ---------------------------------------------------------------------------
extern "C" void kernel_launch(void* const* d_in, const int* in_sizes, int n_in,
                              void* d_out, int out_size)
{
    const float* x    = (const float*)d_in[0];   // [B,L,E]
    const float* wqkv = (const float*)d_in[1];   // [3E,E]
    const float* bqkv = (const float*)d_in[2];   // [3E]
    const float* wout = (const float*)d_in[3];   // [E,E]
    const float* bout = (const float*)d_in[4];   // [E]
    float* out = (float*)d_out;                  // [B,L,E]

    (void)in_sizes; (void)n_in; (void)out_size;

    cudaFuncSetAttribute(fp16_gemm, cudaFuncAttributeMaxDynamicSharedMemorySize,
                         GEMM_SMEM);
    cudaFuncSetAttribute(attn_mma, cudaFuncAttributeMaxDynamicSharedMemorySize,
                         ATTN_SMEM);

    // prep: split x, round weights
    prep_split_x<<<NTOK * EE / 1024, 256>>>(x);
    prep_round<<<QKVN * EE / 1024, 256>>>(wqkv, 0);
    prep_round<<<EE * EE / 1024, 256>>>(wout, 1);

    // QKV projection
    fp16_gemm<<<dim3(QKVN / 128, NTOK / 128), 256, GEMM_SMEM>>>(bqkv, nullptr, 0);

    // banded attention
    attn_mma<<<dim3(LL / 64, HH, BB), 128, ATTN_SMEM>>>();

    // out projection
    fp16_gemm<<<dim3(EE / 128, NTOK / 128), 256, GEMM_SMEM>>>(bout, out, 1);
}

// round 11
// speedup vs baseline: 2.3687x; 1.3924x over previous
#include <cuda_runtime.h>
#include <cuda_fp16.h>
#include <cstdint>
#include <math.h>

// Problem constants
#define BB   2
#define LL   4096
#define EE   512
#define HH   8
#define DD   64
#define WIN  128
#define NTOK (BB*LL)          // 8192
#define QKVN (3*EE)           // 1536

// ---------------------------------------------------------------------------
// Device scratch (half precision dataflow)
// ---------------------------------------------------------------------------
__device__ __half g_Xh[NTOK*EE];                      // x rounded
__device__ __half g_Wq[QKVN*EE];                      // qkv weights (rounded)
__device__ __half g_Wo[EE*EE];                        // out weights (rounded)
__device__ __half g_Qh[BB*HH*LL*DD], g_Ql[BB*HH*LL*DD];  // Q split (attn A-side)
__device__ __half g_Kh[BB*HH*LL*DD];                  // K single half [B,H,L,D]
__device__ __half g_Vt[BB*HH*DD*LL];                  // V transposed [B,H,D,L]
__device__ __half g_Oh[BB*LL*EE];                     // attn out (rounded)

// ---------------------------------------------------------------------------
// Helpers
// ---------------------------------------------------------------------------
__device__ __forceinline__ void mma_f16(float* d, const uint32_t* a,
                                        const uint32_t* b) {
    asm volatile(
        "mma.sync.aligned.m16n8k16.row.col.f32.f16.f16.f32 "
        "{%0,%1,%2,%3}, {%4,%5,%6,%7}, {%8,%9}, {%0,%1,%2,%3};"
        : "+f"(d[0]), "+f"(d[1]), "+f"(d[2]), "+f"(d[3])
        : "r"(a[0]), "r"(a[1]), "r"(a[2]), "r"(a[3]),
          "r"(b[0]), "r"(b[1]));
}

__device__ __forceinline__ uint32_t pack_h2(__half a, __half b) {
    return (uint32_t)__half_as_ushort(a) | ((uint32_t)__half_as_ushort(b) << 16);
}
__device__ __forceinline__ void split_f16(float x, __half& hi, __half& lo) {
    hi = __float2half_rn(x);
    lo = __float2half_rn(x - __half2float(hi));
}

__device__ __forceinline__ uint32_t smem_u32(const void* p) {
    uint32_t a;
    asm("{ .reg .u64 t; cvta.to.shared.u64 t, %1; cvt.u32.u64 %0, t; }"
        : "=r"(a) : "l"(p));
    return a;
}
__device__ __forceinline__ void cp16(uint32_t dst, const void* src) {
    asm volatile("cp.async.ca.shared.global [%0], [%1], 16;"
                 :: "r"(dst), "l"(src));
}
#define CP_COMMIT() asm volatile("cp.async.commit_group;" ::: "memory")

// ---------------------------------------------------------------------------
// Prep: round f32 arrays to half.  which: 0=Wq 1=Wo 2=X
// ---------------------------------------------------------------------------
__global__ __launch_bounds__(256) void prep_round(const float* __restrict__ w,
                                                  int which)
{
    __half* dst = (which == 0) ? g_Wq : (which == 1) ? g_Wo : g_Xh;
    int i = (blockIdx.x * 256 + threadIdx.x) * 4;
    float4 v = *reinterpret_cast<const float4*>(&w[i]);
    uint2 u;
    u.x = pack_h2(__float2half_rn(v.x), __float2half_rn(v.y));
    u.y = pack_h2(__float2half_rn(v.z), __float2half_rn(v.w));
    *reinterpret_cast<uint2*>(&dst[i]) = u;
}

// ---------------------------------------------------------------------------
// fp16 m16n8k16 GEMM: C = Ah[M,K] @ Bh[N,K]^T + bias, K=512.
//   CTA 128x128, BK=32, 8 warps, warp tile 64x32. 3-stage cp.async pipeline.
//   mode 0: A = Xh, B = Wq -> scatter Qh/Ql (x0.125), Kh, Vt epilogues
//   mode 1: A = Oh, B = Wo -> f32 out + bias
//   Smem pitch 40 halves (20 words): fragment banks 20g+c all distinct mod 32.
//   3 stages x 2 planes x 10.25KB = 61.5KB -> 3 CTAs/SM.
// ---------------------------------------------------------------------------
#define HP   40
#define PLH  (128 * HP)                 // halves per plane
#define GEMM_SMEM (6 * PLH * 2)         // 3 stages x (Ah | Bh)

__global__ __launch_bounds__(256) void fp16_gemm(
    const float* __restrict__ bias, float* __restrict__ outp, int mode)
{
    extern __shared__ __half smh[];
    const uint32_t sbase = smem_u32(smh);

    const int tid = threadIdx.x;
    const int m0 = blockIdx.y * 128;
    const int n0 = blockIdx.x * 128;

    const __half* Ahg = mode ? g_Oh : g_Xh;
    const __half* Bg  = mode ? g_Wo : g_Wq;

    const int w    = tid >> 5;
    const int lane = tid & 31;
    const int g    = lane >> 2;
    const int c    = lane & 3;
    const int rm   = (w >> 2) * 64;
    const int cn   = (w & 3) * 32;

    float acc[4][4][4];
    #pragma unroll
    for (int mi = 0; mi < 4; mi++)
        #pragma unroll
        for (int ni = 0; ni < 4; ni++)
            #pragma unroll
            for (int r = 0; r < 4; r++) acc[mi][ni][r] = 0.f;

    const int lrow = tid >> 2;          // 0..63
    const int seg  = (tid & 3) * 8;     // half offset within 32-half row chunk

    auto issue_chunk = [&](int kc, int p) {
        const __half* a  = Ahg + (size_t)m0 * EE + kc * 32;
        const __half* bb = Bg  + (size_t)n0 * EE + kc * 32;
        const uint32_t sb = sbase + (uint32_t)(p * 2 * PLH * 2);
        #pragma unroll
        for (int i = 0; i < 2; i++) {
            int row = lrow + i * 64;
            uint32_t so = (uint32_t)((row * HP + seg) * 2);
            cp16(sb + so,           a  + (size_t)row * EE + seg);
            cp16(sb + PLH * 2 + so, bb + (size_t)row * EE + seg);
        }
    };

    issue_chunk(0, 0); CP_COMMIT();
    issue_chunk(1, 1); CP_COMMIT();

    for (int kc = 0; kc < 16; kc++) {
        const int p = kc % 3;
        if (kc < 15) asm volatile("cp.async.wait_group 1;" ::: "memory");
        else         asm volatile("cp.async.wait_group 0;" ::: "memory");
        __syncthreads();

        if (kc + 2 < 16) {
            issue_chunk(kc + 2, (kc + 2) % 3);
            CP_COMMIT();
        }

        const __half* Asp = smh + p * 2 * PLH;
        const __half* Bsp = Asp + PLH;

        #pragma unroll
        for (int ks = 0; ks < 2; ks++) {
            const int ko = ks * 16 + 2 * c;
            uint32_t af[4][4], bf[4][2];
            #pragma unroll
            for (int mi = 0; mi < 4; mi++) {
                const int ab = (rm + mi * 16 + g) * HP + ko;
                af[mi][0] = *reinterpret_cast<const uint32_t*>(&Asp[ab]);
                af[mi][1] = *reinterpret_cast<const uint32_t*>(&Asp[ab + 8 * HP]);
                af[mi][2] = *reinterpret_cast<const uint32_t*>(&Asp[ab + 8]);
                af[mi][3] = *reinterpret_cast<const uint32_t*>(&Asp[ab + 8 * HP + 8]);
            }
            #pragma unroll
            for (int ni = 0; ni < 4; ni++) {
                const int bb = (cn + ni * 8 + g) * HP + ko;
                bf[ni][0] = *reinterpret_cast<const uint32_t*>(&Bsp[bb]);
                bf[ni][1] = *reinterpret_cast<const uint32_t*>(&Bsp[bb + 8]);
            }
            #pragma unroll
            for (int mi = 0; mi < 4; mi++)
                #pragma unroll
                for (int ni = 0; ni < 4; ni++)
                    mma_f16(acc[mi][ni], af[mi], bf[ni]);
        }
    }

    float bv[4][2];
    #pragma unroll
    for (int ni = 0; ni < 4; ni++) {
        int gn = n0 + cn + ni * 8 + 2 * c;
        bv[ni][0] = bias[gn];
        bv[ni][1] = bias[gn + 1];
    }

    if (mode == 0) {
        const int gnb = n0 + cn;
        const int sel = gnb >> 9;                  // 0=Q 1=K 2=V
        const int h   = (gnb >> 6) & 7;
        #pragma unroll
        for (int mi = 0; mi < 4; mi++) {
            #pragma unroll
            for (int half = 0; half < 2; half++) {
                int gm  = m0 + rm + mi * 16 + g + half * 8;
                int bat = gm >> 12;
                int l   = gm & (LL - 1);
                #pragma unroll
                for (int ni = 0; ni < 4; ni++) {
                    int gn = n0 + cn + ni * 8 + 2 * c;
                    int d  = gn & 63;
                    float f0 = acc[mi][ni][half * 2 + 0] + bv[ni][0];
                    float f1 = acc[mi][ni][half * 2 + 1] + bv[ni][1];
                    if (sel == 0) {
                        f0 *= 0.125f; f1 *= 0.125f;
                        size_t rb = (((size_t)(bat * HH + h) * LL) + l) * DD + d;
                        __half h0, l0, h1, l1;
                        split_f16(f0, h0, l0); split_f16(f1, h1, l1);
                        *reinterpret_cast<uint32_t*>(&g_Qh[rb]) = pack_h2(h0, h1);
                        *reinterpret_cast<uint32_t*>(&g_Ql[rb]) = pack_h2(l0, l1);
                    } else if (sel == 1) {
                        size_t rb = (((size_t)(bat * HH + h) * LL) + l) * DD + d;
                        *reinterpret_cast<uint32_t*>(&g_Kh[rb]) =
                            pack_h2(__float2half_rn(f0), __float2half_rn(f1));
                    } else {
                        size_t vb = (((size_t)(bat * HH + h) * DD) + d) * LL + l;
                        g_Vt[vb]      = __float2half_rn(f0);
                        g_Vt[vb + LL] = __float2half_rn(f1);
                    }
                }
            }
        }
    } else {
        #pragma unroll
        for (int mi = 0; mi < 4; mi++) {
            #pragma unroll
            for (int half = 0; half < 2; half++) {
                int gm = m0 + rm + mi * 16 + g + half * 8;
                #pragma unroll
                for (int ni = 0; ni < 4; ni++) {
                    int gn = n0 + cn + ni * 8 + 2 * c;
                    float2 o;
                    o.x = acc[mi][ni][half * 2 + 0] + bv[ni][0];
                    o.y = acc[mi][ni][half * 2 + 1] + bv[ni][1];
                    *reinterpret_cast<float2*>(&outp[(size_t)gm * EE + gn]) = o;
                }
            }
        }
    }
}

// ---------------------------------------------------------------------------
// Banded flash attention, fp16 m16n8k16 MMA, pure-copy staging.
//   Planes (half, pitch 72): Qh | Ql | Ks | Vt | Ph | Pl. 54 KB -> 4 CTAs/SM.
// ---------------------------------------------------------------------------
#define AP 72
#define HPL (64 * AP)
#define ATTN_SMEM (6 * HPL * 2)

__global__ __launch_bounds__(128, 4) void attn_mma()
{
    extern __shared__ __half smq[];
    __half* Qs = smq;
    __half* Ql = smq + 1 * HPL;
    __half* Ks = smq + 2 * HPL;
    __half* Vt = smq + 3 * HPL;
    __half* Ph = smq + 4 * HPL;
    __half* Pl = smq + 5 * HPL;

    const int q0 = blockIdx.x * 64;
    const int h  = blockIdx.y;
    const int b  = blockIdx.z;
    const int tid  = threadIdx.x;
    const int w    = tid >> 5;
    const int lane = tid & 31;
    const int g    = lane >> 2;
    const int c    = lane & 3;

    const size_t khead = ((size_t)(b * HH + h) * LL) * DD;
    const size_t vhead = ((size_t)(b * HH + h) * DD) * LL;

    // ---- stage Q planes (pure copy) ----
    #pragma unroll
    for (int i = 0; i < 4; i++) {
        int u = tid + i * 128;
        int row = u >> 3;
        int seg = (u & 7) * 8;
        *reinterpret_cast<uint4*>(&Qs[row * AP + seg]) =
            *reinterpret_cast<const uint4*>(&g_Qh[khead + (size_t)(q0 + row) * DD + seg]);
        *reinterpret_cast<uint4*>(&Ql[row * AP + seg]) =
            *reinterpret_cast<const uint4*>(&g_Ql[khead + (size_t)(q0 + row) * DD + seg]);
    }

    float om[2] = {-1e30f, -1e30f};
    float ol[2] = {0.f, 0.f};
    float oacc[8][4];
    #pragma unroll
    for (int nt = 0; nt < 8; nt++)
        #pragma unroll
        for (int r = 0; r < 4; r++) oacc[nt][r] = 0.f;

    __syncthreads();

    const int row_lo = 16 * w + g;
    const int q_lo = q0 + row_lo;
    const int q_hi = q_lo + 8;

    for (int ch = 0; ch < 5; ch++) {
        const int kcc = q0 - 128 + ch * 64;
        if (kcc + 64 <= 0 || kcc >= LL) continue;

        // ---- stage K (natural) and V (pre-transposed) — pure copies ----
        #pragma unroll
        for (int i = 0; i < 4; i++) {
            int u = tid + i * 128;
            int row = u >> 3;
            int seg = (u & 7) * 8;
            int kk = min(max(kcc + row, 0), LL - 1);
            *reinterpret_cast<uint4*>(&Ks[row * AP + seg]) =
                *reinterpret_cast<const uint4*>(&g_Kh[khead + (size_t)kk * DD + seg]);
            int kb = min(max(kcc + seg, 0), LL - 8);
            *reinterpret_cast<uint4*>(&Vt[row * AP + seg]) =
                *reinterpret_cast<const uint4*>(&g_Vt[vhead + (size_t)row * LL + kb]);
        }
        __syncthreads();

        // ---- scores: (Qh + Ql) @ K^T ----
        float sacc[8][4];
        #pragma unroll
        for (int nt = 0; nt < 8; nt++)
            #pragma unroll
            for (int r = 0; r < 4; r++) sacc[nt][r] = 0.f;

        #pragma unroll
        for (int ks = 0; ks < 4; ks++) {
            const int ab = row_lo * AP + ks * 16 + 2 * c;
            uint32_t ah[4], al[4];
            ah[0] = *reinterpret_cast<const uint32_t*>(&Qs[ab]);
            ah[1] = *reinterpret_cast<const uint32_t*>(&Qs[ab + 8 * AP]);
            ah[2] = *reinterpret_cast<const uint32_t*>(&Qs[ab + 8]);
            ah[3] = *reinterpret_cast<const uint32_t*>(&Qs[ab + 8 * AP + 8]);
            al[0] = *reinterpret_cast<const uint32_t*>(&Ql[ab]);
            al[1] = *reinterpret_cast<const uint32_t*>(&Ql[ab + 8 * AP]);
            al[2] = *reinterpret_cast<const uint32_t*>(&Ql[ab + 8]);
            al[3] = *reinterpret_cast<const uint32_t*>(&Ql[ab + 8 * AP + 8]);
            #pragma unroll
            for (int nt = 0; nt < 8; nt++) {
                const int bb = (nt * 8 + g) * AP + ks * 16 + 2 * c;
                uint32_t bf[2];
                bf[0] = *reinterpret_cast<const uint32_t*>(&Ks[bb]);
                bf[1] = *reinterpret_cast<const uint32_t*>(&Ks[bb + 8]);
                mma_f16(sacc[nt], ah, bf);
                mma_f16(sacc[nt], al, bf);
            }
        }

        // ---- mask ----
        #pragma unroll
        for (int nt = 0; nt < 8; nt++) {
            #pragma unroll
            for (int r = 0; r < 4; r++) {
                int key = kcc + nt * 8 + 2 * c + (r & 1);
                int q   = (r >> 1) ? q_hi : q_lo;
                int dlt = q - key;
                bool ok = (key >= 0) && (key < LL) && (dlt != 0) &&
                          (dlt <= WIN) && (dlt >= -WIN);
                if (!ok) sacc[nt][r] = -1e30f;
            }
        }

        // ---- online softmax; write P hi/lo ----
        float mx0 = -1e30f, mx1 = -1e30f;
        #pragma unroll
        for (int nt = 0; nt < 8; nt++) {
            mx0 = fmaxf(mx0, fmaxf(sacc[nt][0], sacc[nt][1]));
            mx1 = fmaxf(mx1, fmaxf(sacc[nt][2], sacc[nt][3]));
        }
        mx0 = fmaxf(mx0, __shfl_xor_sync(0xffffffffu, mx0, 1));
        mx0 = fmaxf(mx0, __shfl_xor_sync(0xffffffffu, mx0, 2));
        mx1 = fmaxf(mx1, __shfl_xor_sync(0xffffffffu, mx1, 1));
        mx1 = fmaxf(mx1, __shfl_xor_sync(0xffffffffu, mx1, 2));

        float m0n = fmaxf(om[0], mx0);
        float m1n = fmaxf(om[1], mx1);
        float alpha0 = __expf(om[0] - m0n);
        float alpha1 = __expf(om[1] - m1n);

        float sum0 = 0.f, sum1 = 0.f;
        #pragma unroll
        for (int nt = 0; nt < 8; nt++) {
            float p0 = __expf(sacc[nt][0] - m0n);
            float p1 = __expf(sacc[nt][1] - m0n);
            float p2 = __expf(sacc[nt][2] - m1n);
            float p3 = __expf(sacc[nt][3] - m1n);
            sum0 += p0 + p1;
            sum1 += p2 + p3;
            __half h0, l0, h1, l1, h2, l2, h3, l3;
            split_f16(p0, h0, l0); split_f16(p1, h1, l1);
            split_f16(p2, h2, l2); split_f16(p3, h3, l3);
            const int pi_lo = row_lo * AP + nt * 8 + 2 * c;
            const int pi_hi = pi_lo + 8 * AP;
            *reinterpret_cast<uint32_t*>(&Ph[pi_lo]) = pack_h2(h0, h1);
            *reinterpret_cast<uint32_t*>(&Pl[pi_lo]) = pack_h2(l0, l1);
            *reinterpret_cast<uint32_t*>(&Ph[pi_hi]) = pack_h2(h2, h3);
            *reinterpret_cast<uint32_t*>(&Pl[pi_hi]) = pack_h2(l2, l3);
        }
        sum0 += __shfl_xor_sync(0xffffffffu, sum0, 1);
        sum0 += __shfl_xor_sync(0xffffffffu, sum0, 2);
        sum1 += __shfl_xor_sync(0xffffffffu, sum1, 1);
        sum1 += __shfl_xor_sync(0xffffffffu, sum1, 2);

        ol[0] = ol[0] * alpha0 + sum0;
        ol[1] = ol[1] * alpha1 + sum1;
        om[0] = m0n;
        om[1] = m1n;

        #pragma unroll
        for (int nt = 0; nt < 8; nt++) {
            oacc[nt][0] *= alpha0;
            oacc[nt][1] *= alpha0;
            oacc[nt][2] *= alpha1;
            oacc[nt][3] *= alpha1;
        }
        __syncwarp();

        // ---- O += (Ph + Pl) @ V ----
        #pragma unroll
        for (int ks = 0; ks < 4; ks++) {
            const int pb = row_lo * AP + ks * 16 + 2 * c;
            uint32_t ah[4], al[4];
            ah[0] = *reinterpret_cast<const uint32_t*>(&Ph[pb]);
            ah[1] = *reinterpret_cast<const uint32_t*>(&Ph[pb + 8 * AP]);
            ah[2] = *reinterpret_cast<const uint32_t*>(&Ph[pb + 8]);
            ah[3] = *reinterpret_cast<const uint32_t*>(&Ph[pb + 8 * AP + 8]);
            al[0] = *reinterpret_cast<const uint32_t*>(&Pl[pb]);
            al[1] = *reinterpret_cast<const uint32_t*>(&Pl[pb + 8 * AP]);
            al[2] = *reinterpret_cast<const uint32_t*>(&Pl[pb + 8]);
            al[3] = *reinterpret_cast<const uint32_t*>(&Pl[pb + 8 * AP + 8]);
            #pragma unroll
            for (int nt = 0; nt < 8; nt++) {
                const int vb = (nt * 8 + g) * AP + ks * 16 + 2 * c;
                uint32_t bf[2];
                bf[0] = *reinterpret_cast<const uint32_t*>(&Vt[vb]);
                bf[1] = *reinterpret_cast<const uint32_t*>(&Vt[vb + 8]);
                mma_f16(oacc[nt], ah, bf);
                mma_f16(oacc[nt], al, bf);
            }
        }
        __syncthreads();
    }

    // ---- epilogue: normalize, round, write Oh [B,L,E] ----
    const float inv0 = 1.f / ol[0];
    const float inv1 = 1.f / ol[1];
    const size_t base_lo = ((size_t)(b * LL + q_lo)) * EE + h * DD;
    const size_t base_hi = ((size_t)(b * LL + q_hi)) * EE + h * DD;
    #pragma unroll
    for (int nt = 0; nt < 8; nt++) {
        int d = nt * 8 + 2 * c;
        *reinterpret_cast<uint32_t*>(&g_Oh[base_lo + d]) =
            pack_h2(__float2half_rn(oacc[nt][0] * inv0),
                    __float2half_rn(oacc[nt][1] * inv0));
        *reinterpret_cast<uint32_t*>(&g_Oh[base_hi + d]) =
            pack_h2(__float2half_rn(oacc[nt][2] * inv1),
                    __float2half_rn(oacc[nt][3] * inv1));
    }
}

// ---------------------------------------------------------------------------
// Entry point
// ---------------------------------------------------------------------------
extern "C" void kernel_launch(void* const* d_in, const int* in_sizes, int n_in,
                              void* d_out, int out_size)
{
    const float* x    = (const float*)d_in[0];   // [B,L,E]
    const float* wqkv = (const float*)d_in[1];   // [3E,E]
    const float* bqkv = (const float*)d_in[2];   // [3E]
    const float* wout = (const float*)d_in[3];   // [E,E]
    const float* bout = (const float*)d_in[4];   // [E]
    float* out = (float*)d_out;                  // [B,L,E]

    (void)in_sizes; (void)n_in; (void)out_size;

    cudaFuncSetAttribute(fp16_gemm, cudaFuncAttributeMaxDynamicSharedMemorySize,
                         GEMM_SMEM);
    cudaFuncSetAttribute(attn_mma, cudaFuncAttributeMaxDynamicSharedMemorySize,
                         ATTN_SMEM);

    // prep: round weights + x to half
    prep_round<<<QKVN * EE / 1024, 256>>>(wqkv, 0);
    prep_round<<<EE * EE / 1024, 256>>>(wout, 1);
    prep_round<<<NTOK * EE / 1024, 256>>>(x, 2);

    // QKV projection
    fp16_gemm<<<dim3(QKVN / 128, NTOK / 128), 256, GEMM_SMEM>>>(bqkv, nullptr, 0);

    // banded attention
    attn_mma<<<dim3(LL / 64, HH, BB), 128, ATTN_SMEM>>>();

    // out projection
    fp16_gemm<<<dim3(EE / 128, NTOK / 128), 256, GEMM_SMEM>>>(bout, out, 1);
}

// round 12
// speedup vs baseline: 2.9026x; 1.2254x over previous
#include <cuda_runtime.h>
#include <cuda_fp16.h>
#include <cstdint>
#include <math.h>

// Problem constants
#define BB   2
#define LL   4096
#define EE   512
#define HH   8
#define DD   64
#define WIN  128
#define NTOK (BB*LL)          // 8192
#define QKVN (3*EE)           // 1536

// ---------------------------------------------------------------------------
// Device scratch (half precision dataflow)
// ---------------------------------------------------------------------------
__device__ __half g_Xh[NTOK*EE];                      // x rounded
__device__ __half g_Wq[QKVN*EE];                      // qkv weights (rounded)
__device__ __half g_Wo[EE*EE];                        // out weights (rounded)
__device__ __half g_Qh[BB*HH*LL*DD];                  // Q rounded (scaled)
__device__ __half g_Kh[BB*HH*LL*DD];                  // K rounded [B,H,L,D]
__device__ __half g_Vt[BB*HH*DD*LL];                  // V transposed [B,H,D,L]
__device__ __half g_Oh[BB*LL*EE];                     // attn out (rounded)

// ---------------------------------------------------------------------------
// Helpers
// ---------------------------------------------------------------------------
__device__ __forceinline__ void mma_f16(float* d, const uint32_t* a,
                                        const uint32_t* b) {
    asm volatile(
        "mma.sync.aligned.m16n8k16.row.col.f32.f16.f16.f32 "
        "{%0,%1,%2,%3}, {%4,%5,%6,%7}, {%8,%9}, {%0,%1,%2,%3};"
        : "+f"(d[0]), "+f"(d[1]), "+f"(d[2]), "+f"(d[3])
        : "r"(a[0]), "r"(a[1]), "r"(a[2]), "r"(a[3]),
          "r"(b[0]), "r"(b[1]));
}

#define LDSM4(r0, r1, r2, r3, addr) \
    asm volatile("ldmatrix.sync.aligned.m8n8.x4.shared.b16 {%0,%1,%2,%3}, [%4];" \
                 : "=r"(r0), "=r"(r1), "=r"(r2), "=r"(r3) : "r"(addr))

__device__ __forceinline__ uint32_t pack_h2(__half a, __half b) {
    return (uint32_t)__half_as_ushort(a) | ((uint32_t)__half_as_ushort(b) << 16);
}

__device__ __forceinline__ uint32_t smem_u32(const void* p) {
    uint32_t a;
    asm("{ .reg .u64 t; cvta.to.shared.u64 t, %1; cvt.u32.u64 %0, t; }"
        : "=r"(a) : "l"(p));
    return a;
}
__device__ __forceinline__ void cp16(uint32_t dst, const void* src) {
    asm volatile("cp.async.ca.shared.global [%0], [%1], 16;"
                 :: "r"(dst), "l"(src));
}
#define CP_COMMIT() asm volatile("cp.async.commit_group;" ::: "memory")

// ---------------------------------------------------------------------------
// Prep: round f32 arrays to half.  which: 0=Wq 1=Wo 2=X
// ---------------------------------------------------------------------------
__global__ __launch_bounds__(256) void prep_round(const float* __restrict__ w,
                                                  int which)
{
    __half* dst = (which == 0) ? g_Wq : (which == 1) ? g_Wo : g_Xh;
    int i = (blockIdx.x * 256 + threadIdx.x) * 4;
    float4 v = *reinterpret_cast<const float4*>(&w[i]);
    uint2 u;
    u.x = pack_h2(__float2half_rn(v.x), __float2half_rn(v.y));
    u.y = pack_h2(__float2half_rn(v.z), __float2half_rn(v.w));
    *reinterpret_cast<uint2*>(&dst[i]) = u;
}

// ---------------------------------------------------------------------------
// fp16 m16n8k16 GEMM: C = Ah[M,K] @ Bh[N,K]^T + bias, K=512.
//   CTA 128x128, BK=64 (8 chunks), 8 warps, warp tile 64x32.
//   3-stage cp.async pipeline, ldmatrix.x4 fragment loads.
//   Pitch 72 halves (144B ≡ 16 mod 128): LDSM row addresses conflict-free.
// ---------------------------------------------------------------------------
#define HP   72
#define PLH  (128 * HP)                 // halves per plane
#define GEMM_SMEM (6 * PLH * 2)         // 3 stages x (A | B) = 108 KB

__global__ __launch_bounds__(256) void fp16_gemm(
    const float* __restrict__ bias, float* __restrict__ outp, int mode)
{
    extern __shared__ __half smh[];
    const uint32_t sbase = smem_u32(smh);

    const int tid = threadIdx.x;
    const int m0 = blockIdx.y * 128;
    const int n0 = blockIdx.x * 128;

    const __half* Ahg = mode ? g_Oh : g_Xh;
    const __half* Bg  = mode ? g_Wo : g_Wq;

    const int w    = tid >> 5;
    const int lane = tid & 31;
    const int g    = lane >> 2;
    const int c    = lane & 3;
    const int rm   = (w >> 2) * 64;
    const int cn   = (w & 3) * 32;

    // ldmatrix lane-address components
    const int arow = lane & 15;
    const int acol = (lane >> 4) * 8;
    const int bno  = (lane & 7) + ((lane >> 4) << 3);
    const int bko  = ((lane >> 3) & 1) * 8;

    float acc[4][4][4];
    #pragma unroll
    for (int mi = 0; mi < 4; mi++)
        #pragma unroll
        for (int ni = 0; ni < 4; ni++)
            #pragma unroll
            for (int r = 0; r < 4; r++) acc[mi][ni][r] = 0.f;

    const int lrow = tid >> 2;           // 0..63
    const int lcol = (tid & 3) * 16;     // 0,16,32,48 (halves)

    auto issue_chunk = [&](int kc, int p) {
        const __half* a  = Ahg + (size_t)m0 * EE + kc * 64;
        const __half* bb = Bg  + (size_t)n0 * EE + kc * 64;
        const uint32_t sb = sbase + (uint32_t)(p * 2 * PLH * 2);
        #pragma unroll
        for (int i = 0; i < 2; i++) {
            int row = lrow + i * 64;
            uint32_t so = (uint32_t)((row * HP + lcol) * 2);
            cp16(sb + so,                a  + (size_t)row * EE + lcol);
            cp16(sb + so + 16,           a  + (size_t)row * EE + lcol + 8);
            cp16(sb + PLH * 2 + so,      bb + (size_t)row * EE + lcol);
            cp16(sb + PLH * 2 + so + 16, bb + (size_t)row * EE + lcol + 8);
        }
    };

    issue_chunk(0, 0); CP_COMMIT();
    issue_chunk(1, 1); CP_COMMIT();

    for (int kc = 0; kc < 8; kc++) {
        const int p = kc % 3;
        if (kc < 7) asm volatile("cp.async.wait_group 1;" ::: "memory");
        else        asm volatile("cp.async.wait_group 0;" ::: "memory");
        __syncthreads();

        if (kc + 2 < 8) {
            issue_chunk(kc + 2, (kc + 2) % 3);
            CP_COMMIT();
        }

        const uint32_t sA = sbase + (uint32_t)(p * 2 * PLH * 2);
        const uint32_t sB = sA + (uint32_t)(PLH * 2);

        #pragma unroll
        for (int ks = 0; ks < 4; ks++) {
            uint32_t af[4][4], bf[4][2];
            #pragma unroll
            for (int mi = 0; mi < 4; mi++) {
                uint32_t ad = sA + (uint32_t)(((rm + mi * 16 + arow) * HP
                                               + ks * 16 + acol) * 2);
                LDSM4(af[mi][0], af[mi][1], af[mi][2], af[mi][3], ad);
            }
            #pragma unroll
            for (int p2 = 0; p2 < 2; p2++) {
                uint32_t bd = sB + (uint32_t)(((cn + p2 * 16 + bno) * HP
                                               + ks * 16 + bko) * 2);
                LDSM4(bf[2 * p2][0], bf[2 * p2][1],
                      bf[2 * p2 + 1][0], bf[2 * p2 + 1][1], bd);
            }
            #pragma unroll
            for (int mi = 0; mi < 4; mi++)
                #pragma unroll
                for (int ni = 0; ni < 4; ni++)
                    mma_f16(acc[mi][ni], af[mi], bf[ni]);
        }
    }

    float bv[4][2];
    #pragma unroll
    for (int ni = 0; ni < 4; ni++) {
        int gn = n0 + cn + ni * 8 + 2 * c;
        bv[ni][0] = bias[gn];
        bv[ni][1] = bias[gn + 1];
    }

    if (mode == 0) {
        const int gnb = n0 + cn;
        const int sel = gnb >> 9;                  // 0=Q 1=K 2=V
        const int h   = (gnb >> 6) & 7;
        #pragma unroll
        for (int mi = 0; mi < 4; mi++) {
            #pragma unroll
            for (int half = 0; half < 2; half++) {
                int gm  = m0 + rm + mi * 16 + g + half * 8;
                int bat = gm >> 12;
                int l   = gm & (LL - 1);
                #pragma unroll
                for (int ni = 0; ni < 4; ni++) {
                    int gn = n0 + cn + ni * 8 + 2 * c;
                    int d  = gn & 63;
                    float f0 = acc[mi][ni][half * 2 + 0] + bv[ni][0];
                    float f1 = acc[mi][ni][half * 2 + 1] + bv[ni][1];
                    if (sel == 0) {
                        f0 *= 0.125f; f1 *= 0.125f;
                        size_t rb = (((size_t)(bat * HH + h) * LL) + l) * DD + d;
                        *reinterpret_cast<uint32_t*>(&g_Qh[rb]) =
                            pack_h2(__float2half_rn(f0), __float2half_rn(f1));
                    } else if (sel == 1) {
                        size_t rb = (((size_t)(bat * HH + h) * LL) + l) * DD + d;
                        *reinterpret_cast<uint32_t*>(&g_Kh[rb]) =
                            pack_h2(__float2half_rn(f0), __float2half_rn(f1));
                    } else {
                        size_t vb = (((size_t)(bat * HH + h) * DD) + d) * LL + l;
                        g_Vt[vb]      = __float2half_rn(f0);
                        g_Vt[vb + LL] = __float2half_rn(f1);
                    }
                }
            }
        }
    } else {
        #pragma unroll
        for (int mi = 0; mi < 4; mi++) {
            #pragma unroll
            for (int half = 0; half < 2; half++) {
                int gm = m0 + rm + mi * 16 + g + half * 8;
                #pragma unroll
                for (int ni = 0; ni < 4; ni++) {
                    int gn = n0 + cn + ni * 8 + 2 * c;
                    float2 o;
                    o.x = acc[mi][ni][half * 2 + 0] + bv[ni][0];
                    o.y = acc[mi][ni][half * 2 + 1] + bv[ni][1];
                    *reinterpret_cast<float2*>(&outp[(size_t)gm * EE + gn]) = o;
                }
            }
        }
    }
}

// ---------------------------------------------------------------------------
// Banded flash attention, fp16 m16n8k16, single-rounded operands, ldmatrix.
//   Planes (half, pitch 72): Qs | Ks | Vt | Ph. 36 KB -> 4+ CTAs/SM.
// ---------------------------------------------------------------------------
#define AP 72
#define HPL (64 * AP)
#define ATTN_SMEM (4 * HPL * 2)

__global__ __launch_bounds__(128, 4) void attn_mma()
{
    extern __shared__ __half smq[];
    const uint32_t sQ = smem_u32(smq);
    const uint32_t sK = sQ + 1 * HPL * 2;
    const uint32_t sV = sQ + 2 * HPL * 2;
    const uint32_t sP = sQ + 3 * HPL * 2;
    __half* Qs = smq;
    __half* Ks = smq + 1 * HPL;
    __half* Vt = smq + 2 * HPL;
    __half* Ph = smq + 3 * HPL;

    const int q0 = blockIdx.x * 64;
    const int h  = blockIdx.y;
    const int b  = blockIdx.z;
    const int tid  = threadIdx.x;
    const int w    = tid >> 5;
    const int lane = tid & 31;
    const int g    = lane >> 2;
    const int c    = lane & 3;

    const int arow = lane & 15;
    const int acol = (lane >> 4) * 8;
    const int bno  = (lane & 7) + ((lane >> 4) << 3);
    const int bko  = ((lane >> 3) & 1) * 8;

    const size_t khead = ((size_t)(b * HH + h) * LL) * DD;
    const size_t vhead = ((size_t)(b * HH + h) * DD) * LL;

    // ---- stage Q (pure copy) ----
    #pragma unroll
    for (int i = 0; i < 4; i++) {
        int u = tid + i * 128;
        int row = u >> 3;
        int seg = (u & 7) * 8;
        *reinterpret_cast<uint4*>(&Qs[row * AP + seg]) =
            *reinterpret_cast<const uint4*>(&g_Qh[khead + (size_t)(q0 + row) * DD + seg]);
    }

    float om[2] = {-1e30f, -1e30f};
    float ol[2] = {0.f, 0.f};
    float oacc[8][4];
    #pragma unroll
    for (int nt = 0; nt < 8; nt++)
        #pragma unroll
        for (int r = 0; r < 4; r++) oacc[nt][r] = 0.f;

    __syncthreads();

    const int row_lo = 16 * w + g;
    const int q_lo = q0 + row_lo;
    const int q_hi = q_lo + 8;

    for (int ch = 0; ch < 5; ch++) {
        const int kcc = q0 - 128 + ch * 64;
        if (kcc + 64 <= 0 || kcc >= LL) continue;

        // ---- stage K (natural) and V (pre-transposed) — pure copies ----
        #pragma unroll
        for (int i = 0; i < 4; i++) {
            int u = tid + i * 128;
            int row = u >> 3;
            int seg = (u & 7) * 8;
            int kk = min(max(kcc + row, 0), LL - 1);
            *reinterpret_cast<uint4*>(&Ks[row * AP + seg]) =
                *reinterpret_cast<const uint4*>(&g_Kh[khead + (size_t)kk * DD + seg]);
            int kb = min(max(kcc + seg, 0), LL - 8);
            *reinterpret_cast<uint4*>(&Vt[row * AP + seg]) =
                *reinterpret_cast<const uint4*>(&g_Vt[vhead + (size_t)row * LL + kb]);
        }
        __syncthreads();

        // ---- scores: Q @ K^T (ldmatrix + single MMA per tile) ----
        float sacc[8][4];
        #pragma unroll
        for (int nt = 0; nt < 8; nt++)
            #pragma unroll
            for (int r = 0; r < 4; r++) sacc[nt][r] = 0.f;

        #pragma unroll
        for (int ks = 0; ks < 4; ks++) {
            uint32_t af[4], kb2[8][2];
            uint32_t ad = sQ + (uint32_t)(((16 * w + arow) * AP + ks * 16 + acol) * 2);
            LDSM4(af[0], af[1], af[2], af[3], ad);
            #pragma unroll
            for (int p2 = 0; p2 < 4; p2++) {
                uint32_t bd = sK + (uint32_t)(((p2 * 16 + bno) * AP + ks * 16 + bko) * 2);
                LDSM4(kb2[2 * p2][0], kb2[2 * p2][1],
                      kb2[2 * p2 + 1][0], kb2[2 * p2 + 1][1], bd);
            }
            #pragma unroll
            for (int nt = 0; nt < 8; nt++)
                mma_f16(sacc[nt], af, kb2[nt]);
        }

        // ---- mask ----
        #pragma unroll
        for (int nt = 0; nt < 8; nt++) {
            #pragma unroll
            for (int r = 0; r < 4; r++) {
                int key = kcc + nt * 8 + 2 * c + (r & 1);
                int q   = (r >> 1) ? q_hi : q_lo;
                int dlt = q - key;
                bool ok = (key >= 0) && (key < LL) && (dlt != 0) &&
                          (dlt <= WIN) && (dlt >= -WIN);
                if (!ok) sacc[nt][r] = -1e30f;
            }
        }

        // ---- online softmax; write P (single fp16) ----
        float mx0 = -1e30f, mx1 = -1e30f;
        #pragma unroll
        for (int nt = 0; nt < 8; nt++) {
            mx0 = fmaxf(mx0, fmaxf(sacc[nt][0], sacc[nt][1]));
            mx1 = fmaxf(mx1, fmaxf(sacc[nt][2], sacc[nt][3]));
        }
        mx0 = fmaxf(mx0, __shfl_xor_sync(0xffffffffu, mx0, 1));
        mx0 = fmaxf(mx0, __shfl_xor_sync(0xffffffffu, mx0, 2));
        mx1 = fmaxf(mx1, __shfl_xor_sync(0xffffffffu, mx1, 1));
        mx1 = fmaxf(mx1, __shfl_xor_sync(0xffffffffu, mx1, 2));

        float m0n = fmaxf(om[0], mx0);
        float m1n = fmaxf(om[1], mx1);
        float alpha0 = __expf(om[0] - m0n);
        float alpha1 = __expf(om[1] - m1n);

        float sum0 = 0.f, sum1 = 0.f;
        #pragma unroll
        for (int nt = 0; nt < 8; nt++) {
            float p0 = __expf(sacc[nt][0] - m0n);
            float p1 = __expf(sacc[nt][1] - m0n);
            float p2 = __expf(sacc[nt][2] - m1n);
            float p3 = __expf(sacc[nt][3] - m1n);
            sum0 += p0 + p1;
            sum1 += p2 + p3;
            const int pi_lo = row_lo * AP + nt * 8 + 2 * c;
            const int pi_hi = pi_lo + 8 * AP;
            *reinterpret_cast<uint32_t*>(&Ph[pi_lo]) =
                pack_h2(__float2half_rn(p0), __float2half_rn(p1));
            *reinterpret_cast<uint32_t*>(&Ph[pi_hi]) =
                pack_h2(__float2half_rn(p2), __float2half_rn(p3));
        }
        sum0 += __shfl_xor_sync(0xffffffffu, sum0, 1);
        sum0 += __shfl_xor_sync(0xffffffffu, sum0, 2);
        sum1 += __shfl_xor_sync(0xffffffffu, sum1, 1);
        sum1 += __shfl_xor_sync(0xffffffffu, sum1, 2);

        ol[0] = ol[0] * alpha0 + sum0;
        ol[1] = ol[1] * alpha1 + sum1;
        om[0] = m0n;
        om[1] = m1n;

        #pragma unroll
        for (int nt = 0; nt < 8; nt++) {
            oacc[nt][0] *= alpha0;
            oacc[nt][1] *= alpha0;
            oacc[nt][2] *= alpha1;
            oacc[nt][3] *= alpha1;
        }
        __syncwarp();   // P rows are warp-private

        // ---- O += P @ V (ldmatrix + single MMA per tile) ----
        #pragma unroll
        for (int ks = 0; ks < 4; ks++) {
            uint32_t af[4], vb2[8][2];
            uint32_t ad = sP + (uint32_t)(((16 * w + arow) * AP + ks * 16 + acol) * 2);
            LDSM4(af[0], af[1], af[2], af[3], ad);
            #pragma unroll
            for (int p2 = 0; p2 < 4; p2++) {
                uint32_t bd = sV + (uint32_t)(((p2 * 16 + bno) * AP + ks * 16 + bko) * 2);
                LDSM4(vb2[2 * p2][0], vb2[2 * p2][1],
                      vb2[2 * p2 + 1][0], vb2[2 * p2 + 1][1], bd);
            }
            #pragma unroll
            for (int nt = 0; nt < 8; nt++)
                mma_f16(oacc[nt], af, vb2[nt]);
        }
        __syncthreads();   // protect Ks/Vt before next chunk staging
    }

    // ---- epilogue: normalize, round, write Oh [B,L,E] ----
    const float inv0 = 1.f / ol[0];
    const float inv1 = 1.f / ol[1];
    const size_t base_lo = ((size_t)(b * LL + q_lo)) * EE + h * DD;
    const size_t base_hi = ((size_t)(b * LL + q_hi)) * EE + h * DD;
    #pragma unroll
    for (int nt = 0; nt < 8; nt++) {
        int d = nt * 8 + 2 * c;
        *reinterpret_cast<uint32_t*>(&g_Oh[base_lo + d]) =
            pack_h2(__float2half_rn(oacc[nt][0] * inv0),
                    __float2half_rn(oacc[nt][1] * inv0));
        *reinterpret_cast<uint32_t*>(&g_Oh[base_hi + d]) =
            pack_h2(__float2half_rn(oacc[nt][2] * inv1),
                    __float2half_rn(oacc[nt][3] * inv1));
    }
}

// ---------------------------------------------------------------------------
// Entry point
// ---------------------------------------------------------------------------
extern "C" void kernel_launch(void* const* d_in, const int* in_sizes, int n_in,
                              void* d_out, int out_size)
{
    const float* x    = (const float*)d_in[0];   // [B,L,E]
    const float* wqkv = (const float*)d_in[1];   // [3E,E]
    const float* bqkv = (const float*)d_in[2];   // [3E]
    const float* wout = (const float*)d_in[3];   // [E,E]
    const float* bout = (const float*)d_in[4];   // [E]
    float* out = (float*)d_out;                  // [B,L,E]

    (void)in_sizes; (void)n_in; (void)out_size;

    cudaFuncSetAttribute(fp16_gemm, cudaFuncAttributeMaxDynamicSharedMemorySize,
                         GEMM_SMEM);
    cudaFuncSetAttribute(attn_mma, cudaFuncAttributeMaxDynamicSharedMemorySize,
                         ATTN_SMEM);

    // prep: round weights + x to half
    prep_round<<<QKVN * EE / 1024, 256>>>(wqkv, 0);
    prep_round<<<EE * EE / 1024, 256>>>(wout, 1);
    prep_round<<<NTOK * EE / 1024, 256>>>(x, 2);

    // QKV projection
    fp16_gemm<<<dim3(QKVN / 128, NTOK / 128), 256, GEMM_SMEM>>>(bqkv, nullptr, 0);

    // banded attention
    attn_mma<<<dim3(LL / 64, HH, BB), 128, ATTN_SMEM>>>();

    // out projection
    fp16_gemm<<<dim3(EE / 128, NTOK / 128), 256, GEMM_SMEM>>>(bout, out, 1);
}